// round 8
// baseline (speedup 1.0000x reference)
#include <cuda_runtime.h>
#include <cuda_bf16.h>
#include <cuda_fp16.h>
#include <math.h>
#include <stdint.h>

#define N_NODES  50000
#define N_EDGES  600000
#define NF       128
#define N_GRAPHS 256
#define DIM      95
#define N_OUT    12
#define N_ITERS  10
#define BN_EPS   1e-5f
#define SCAN_NBLK 196            // 50000/256 chunks
#define NTILES   391             // ceil(50000/128)
#define PRO_GRID 148

// ---------------- scratch (zero-initialized at load; self-cleaning) --------
__device__ unsigned g_ahi[N_NODES * 64];   // bf16x2 packed: (x+agg) hi
__device__ unsigned g_alo[N_NODES * 64];
__device__ unsigned g_x16[N_NODES * 64];   // x as half2 pairs (2 uints = 4 feats)
__device__ int   g_counts[N_NODES];        // zeroed in scan phase
__device__ int   g_offsets[N_NODES + 1];   // chunk-local prefixes
__device__ int   g_cursor[N_NODES];
__device__ int   g_srcidx[N_EDGES];
__device__ int   g_bsums[SCAN_NBLK];
__device__ int   g_bpre[SCAN_NBLK];
__device__ float g_stats[2 * NF];          // zeroed by recur_mlp last block
__device__ float g_gsum[N_GRAPHS * NF];    // zeroed by its recur_mlp block
__device__ int   g_arrive;                 // prologue grid barrier (self-reset)
__device__ int   g_tickR;                  // recur ticket (self-reset)

// ---------------- helpers ----------------
__device__ __forceinline__ uint32_t smem_u32(const void* p) {
    uint32_t a;
    asm("{ .reg .u64 t; cvta.to.shared.u64 t, %1; cvt.u32.u64 %0, t; }" : "=r"(a) : "l"(p));
    return a;
}
__device__ __forceinline__ void split_bf(float v, unsigned short& h, unsigned short& l) {
    __nv_bfloat16 hb = __float2bfloat16(v);
    float r = v - __bfloat162float(hb);
    __nv_bfloat16 lb = __float2bfloat16(r);
    h = __bfloat16_as_ushort(hb);
    l = __bfloat16_as_ushort(lb);
}
__device__ __forceinline__ void ldsm_x4(uint32_t* r, uint32_t addr) {
    asm volatile("ldmatrix.sync.aligned.m8n8.x4.shared.b16 {%0,%1,%2,%3}, [%4];"
        : "=r"(r[0]), "=r"(r[1]), "=r"(r[2]), "=r"(r[3]) : "r"(addr));
}
__device__ __forceinline__ void ldsm_x4_t(uint32_t* r, uint32_t addr) {
    asm volatile("ldmatrix.sync.aligned.m8n8.x4.trans.shared.b16 {%0,%1,%2,%3}, [%4];"
        : "=r"(r[0]), "=r"(r[1]), "=r"(r[2]), "=r"(r[3]) : "r"(addr));
}
__device__ __forceinline__ void mma_bf16(float* c, const uint32_t* a,
                                         uint32_t b0, uint32_t b1) {
    asm volatile("mma.sync.aligned.m16n8k16.row.col.f32.bf16.bf16.f32 "
        "{%0,%1,%2,%3}, {%4,%5,%6,%7}, {%8,%9}, {%0,%1,%2,%3};"
        : "+f"(c[0]), "+f"(c[1]), "+f"(c[2]), "+f"(c[3])
        : "r"(a[0]), "r"(a[1]), "r"(a[2]), "r"(a[3]), "r"(b0), "r"(b1));
}
__device__ __forceinline__ void cp_async16(uint32_t dst, const void* src, int srcsz) {
    asm volatile("cp.async.cg.shared.global [%0], [%1], 16, %2;"
        :: "r"(dst), "l"(src), "r"(srcsz) : "memory");
}
#define CP_COMMIT() asm volatile("cp.async.commit_group;" ::: "memory")
#define CP_WAIT0()  asm volatile("cp.async.wait_group 0;" ::: "memory")
__device__ __forceinline__ int load_index(const void* p, long long i, int is64) {
    if (is64) return (int)((const long long*)p)[i];
    return ((const int*)p)[i];
}
__device__ __forceinline__ int probe_is64(const void* p) {
    const int* w32 = (const int*)p;
    int bad = 0;
    for (int j = threadIdx.x; j < 1024; j += blockDim.x)
        if (w32[2 * j + 1] != 0) bad = 1;
    return !__syncthreads_or(bad);
}
// grid barrier: monotonic arrive counter within one launch
__device__ __forceinline__ void grid_bar(int phase) {
    __syncthreads();
    if (threadIdx.x == 0) {
        __threadfence();
        atomicAdd(&g_arrive, 1);
        int target = phase * (int)gridDim.x;
        while (atomicAdd(&g_arrive, 0) < target) __nanosleep(64);
        __threadfence();
    }
    __syncthreads();
}

// ---------------- persistent prologue: count+convert / scan / scatter / agg
__global__ __launch_bounds__(256, 1) void prologue_kernel(
        const float4* __restrict__ x4, const void* __restrict__ ei) {
    __shared__ int ws[8];
    int t = threadIdx.x, lane = t & 31, w = t >> 5;
    int gtid = blockIdx.x * 256 + t;
    int gstride = gridDim.x * 256;
    int is64 = probe_is64(ei);

    // ---- phase 1: degree count + x -> fp16 conversion ----
    for (int e = gtid; e < N_EDGES; e += gstride) {
        int d = load_index(ei, (long long)N_EDGES + e, is64);
        atomicAdd(&g_counts[d], 1);
    }
    {
        uint2* x16v2 = (uint2*)g_x16;
        for (int i = gtid; i < N_NODES * 32; i += gstride) {
            float4 v = x4[i];
            __half2 a = __floats2half2_rn(v.x, v.y);
            __half2 b = __floats2half2_rn(v.z, v.w);
            uint2 u;
            u.x = *(unsigned*)&a;
            u.y = *(unsigned*)&b;
            x16v2[i] = u;
        }
    }
    grid_bar(1);

    // ---- phase 2: per-chunk local exclusive scans ----
    for (int chunk = blockIdx.x; chunk < SCAN_NBLK; chunk += gridDim.x) {
        int i = chunk * 256 + t;
        int v = (i < N_NODES) ? g_counts[i] : 0;
        if (i < N_NODES) g_counts[i] = 0;      // self-clean
        int x = v;
#pragma unroll
        for (int o = 1; o < 32; o <<= 1) {
            int y = __shfl_up_sync(0xffffffffu, x, o);
            if (lane >= o) x += y;
        }
        if (lane == 31) ws[w] = x;
        __syncthreads();
        if (w == 0) {
            int y = (lane < 8) ? ws[lane] : 0;
#pragma unroll
            for (int o = 1; o < 32; o <<= 1) {
                int z = __shfl_up_sync(0xffffffffu, y, o);
                if (lane >= o) y += z;
            }
            if (lane < 8) ws[lane] = y;
        }
        __syncthreads();
        int pre = ((w > 0) ? ws[w - 1] : 0) + x - v;
        if (i <= N_NODES) g_offsets[i] = pre;
        if (i < N_NODES) g_cursor[i] = pre;
        if (t == 255) g_bsums[chunk] = ws[7];
        __syncthreads();
    }
    grid_bar(2);

    // ---- phase 3: block 0 scans the 196 chunk sums ----
    if (blockIdx.x == 0) {
        int v2 = (t < SCAN_NBLK) ? g_bsums[t] : 0;
        int x2 = v2;
#pragma unroll
        for (int o = 1; o < 32; o <<= 1) {
            int y = __shfl_up_sync(0xffffffffu, x2, o);
            if (lane >= o) x2 += y;
        }
        if (lane == 31) ws[w] = x2;
        __syncthreads();
        if (w == 0) {
            int y = (lane < 8) ? ws[lane] : 0;
#pragma unroll
            for (int o = 1; o < 32; o <<= 1) {
                int z = __shfl_up_sync(0xffffffffu, y, o);
                if (lane >= o) y += z;
            }
            if (lane < 8) ws[lane] = y;
        }
        __syncthreads();
        if (t < SCAN_NBLK) g_bpre[t] = ((w > 0) ? ws[w - 1] : 0) + x2 - v2;
    }
    grid_bar(3);

    // ---- phase 4: scatter edges into CSR ----
    for (int e = gtid; e < N_EDGES; e += gstride) {
        int s = load_index(ei, e, is64);
        int d = load_index(ei, (long long)N_EDGES + e, is64);
        int pos = g_bpre[d >> 8] + atomicAdd(&g_cursor[d], 1);
        g_srcidx[pos] = s;
    }
    grid_bar(4);

    // ---- phase 5: aggregation (warp per node, fp16 gather + fp32 self) ----
    {
        const uint2* x16v2 = (const uint2*)g_x16;
        for (int node = blockIdx.x * 8 + w; node < N_NODES; node += gridDim.x * 8) {
            float4 self = x4[node * 32 + lane];
            float acc0 = self.x, acc1 = self.y, acc2 = self.z, acc3 = self.w;
            int e0 = g_offsets[node] + g_bpre[node >> 8];
            int e1 = g_offsets[node + 1] + g_bpre[(node + 1) >> 8];
            int e = e0;
            int n4 = e0 + ((e1 - e0) & ~3);
            for (; e < n4; e += 4) {
                int s0 = g_srcidx[e], s1 = g_srcidx[e + 1];
                int s2 = g_srcidx[e + 2], s3 = g_srcidx[e + 3];
                uint2 u0 = x16v2[s0 * 32 + lane];
                uint2 u1 = x16v2[s1 * 32 + lane];
                uint2 u2 = x16v2[s2 * 32 + lane];
                uint2 u3 = x16v2[s3 * 32 + lane];
                float2 f0a = __half22float2(*(__half2*)&u0.x);
                float2 f0b = __half22float2(*(__half2*)&u0.y);
                float2 f1a = __half22float2(*(__half2*)&u1.x);
                float2 f1b = __half22float2(*(__half2*)&u1.y);
                float2 f2a = __half22float2(*(__half2*)&u2.x);
                float2 f2b = __half22float2(*(__half2*)&u2.y);
                float2 f3a = __half22float2(*(__half2*)&u3.x);
                float2 f3b = __half22float2(*(__half2*)&u3.y);
                acc0 += f0a.x + f1a.x + f2a.x + f3a.x;
                acc1 += f0a.y + f1a.y + f2a.y + f3a.y;
                acc2 += f0b.x + f1b.x + f2b.x + f3b.x;
                acc3 += f0b.y + f1b.y + f2b.y + f3b.y;
            }
            for (; e < e1; e++) {
                int s = g_srcidx[e];
                uint2 u = x16v2[s * 32 + lane];
                float2 fa = __half22float2(*(__half2*)&u.x);
                float2 fb = __half22float2(*(__half2*)&u.y);
                acc0 += fa.x; acc1 += fa.y; acc2 += fb.x; acc3 += fb.y;
            }
            float vv[4] = {acc0, acc1, acc2, acc3};
            unsigned short h[4], l[4];
#pragma unroll
            for (int i = 0; i < 4; i++) split_bf(vv[i], h[i], l[i]);
            uint2 hv = make_uint2((unsigned)h[0] | ((unsigned)h[1] << 16),
                                  (unsigned)h[2] | ((unsigned)h[3] << 16));
            uint2 lv = make_uint2((unsigned)l[0] | ((unsigned)l[1] << 16),
                                  (unsigned)l[2] | ((unsigned)l[3] << 16));
            ((uint2*)g_ahi)[node * 32 + lane] = hv;
            ((uint2*)g_alo)[node * 32 + lane] = lv;
        }
    }

    // completion ticket: last block resets the barrier counter
    __syncthreads();
    if (t == 0) {
        __threadfence();
        if (atomicAdd(&g_arrive, 1) == 5 * (int)gridDim.x - 1) g_arrive = 0;
    }
}

// ---------------- fused dual GEMM (nn1 both layers) ------------------------
#define SA      0                 /* A/t1 tile: hi @ +0, lo @ +34816 */
#define ALO_OFF 34816
#define SWA_HI  69632
#define SWA_LO  104448
#define SWB_HI  139264
#define SWB_LO  174080
#define SBIAS1  208896
#define SBIAS2  209408
#define SBATCH  209920
#define GEMM_SMEM 210432

__device__ __forceinline__ void mainloop_128(uint32_t sbase, uint32_t wBase,
                                             uint32_t lOff, int m0, int n0,
                                             float c[2][8][4]) {
#pragma unroll
    for (int mh = 0; mh < 2; mh++)
#pragma unroll
        for (int j = 0; j < 8; j++)
#pragma unroll
            for (int q = 0; q < 4; q++) c[mh][j][q] = 0.f;

#pragma unroll 1
    for (int ks = 0; ks < 8; ks++) {
        uint32_t ah[2][4], al[2][4];
#pragma unroll
        for (int mh = 0; mh < 2; mh++) {
            uint32_t aa = sbase + SA + (uint32_t)(m0 + mh * 16) * 272 +
                          (uint32_t)ks * 32 + lOff;
            ldsm_x4(ah[mh], aa);
            ldsm_x4(al[mh], aa + ALO_OFF);
        }
#pragma unroll
        for (int nj = 0; nj < 4; nj++) {
            uint32_t bh[4], bl[4];
            uint32_t ba = sbase + wBase + (uint32_t)ks * 16 * 272 +
                          (uint32_t)(n0 + nj * 16) * 2 + lOff;
            ldsm_x4_t(bh, ba);
            ldsm_x4_t(bl, ba + ALO_OFF);
#pragma unroll
            for (int mh = 0; mh < 2; mh++) {
                mma_bf16(c[mh][2 * nj],     ah[mh], bh[0], bh[1]);
                mma_bf16(c[mh][2 * nj + 1], ah[mh], bh[2], bh[3]);
                mma_bf16(c[mh][2 * nj],     ah[mh], bl[0], bl[1]);
                mma_bf16(c[mh][2 * nj + 1], ah[mh], bl[2], bl[3]);
                mma_bf16(c[mh][2 * nj],     al[mh], bh[0], bh[1]);
                mma_bf16(c[mh][2 * nj + 1], al[mh], bh[2], bh[3]);
            }
        }
    }
}

__global__ __launch_bounds__(256, 1) void gemm_fused_kernel(
        const unsigned* __restrict__ Ahi, const unsigned* __restrict__ Alo,
        const float* __restrict__ W1a, const float* __restrict__ b1a,
        const float* __restrict__ W1b, const float* __restrict__ b1b,
        const void* __restrict__ batch, int M) {
    extern __shared__ char smem[];
    uint32_t sbase = smem_u32(smem);
    float* sBias1 = (float*)(smem + SBIAS1);
    float* sBias2 = (float*)(smem + SBIAS2);
    int* sB = (int*)(smem + SBATCH);
    int t = threadIdx.x;
    int lane = t & 31;
    int w = t >> 5;
    int wr = w >> 1, wc = w & 1;
    int m0 = wr * 32, n0 = wc * 64;
    int is64 = probe_is64(batch);

    {
        int tile0 = blockIdx.x;
        if (tile0 < NTILES) {
            int row0 = tile0 << 7;
            for (int idx = t; idx < 2048; idx += 256) {
                int r = idx >> 4, c4 = idx & 15;
                int gr = row0 + r;
                int ok = (gr < M) ? 16 : 0;
                int grc = ok ? gr : 0;
                cp_async16(sbase + SA + r * 272 + c4 * 16, Ahi + grc * 64 + c4 * 4, ok);
                cp_async16(sbase + SA + ALO_OFF + r * 272 + c4 * 16,
                           Alo + grc * 64 + c4 * 4, ok);
            }
        }
        CP_COMMIT();
    }

    for (int idx = t; idx < 128 * 128; idx += 256) {
        int k = idx >> 7, n = idx & 127;
        unsigned short h, l;
        split_bf(W1a[idx], h, l);
        *(unsigned short*)(smem + SWA_HI + (k * 136 + n) * 2) = h;
        *(unsigned short*)(smem + SWA_LO + (k * 136 + n) * 2) = l;
        split_bf(W1b[idx], h, l);
        *(unsigned short*)(smem + SWB_HI + (k * 136 + n) * 2) = h;
        *(unsigned short*)(smem + SWB_LO + (k * 136 + n) * 2) = l;
    }
    if (t < 128) { sBias1[t] = b1a[t]; sBias2[t] = b1b[t]; }

    int lrow = (lane & 7) + ((lane >> 3) & 1) * 8;
    int lcol = (lane >> 4) * 8;
    uint32_t lOff = (uint32_t)(lrow * 136 + lcol) * 2;
    int er = lane >> 2;
    int ec = 2 * (lane & 3);

    for (int tile = blockIdx.x; tile < NTILES; tile += gridDim.x) {
        int row0 = tile << 7;
        CP_WAIT0();
        __syncthreads();

        float c[2][8][4];
        mainloop_128(sbase, SWA_HI, lOff, m0, n0, c);
        __syncthreads();

#pragma unroll
        for (int mh = 0; mh < 2; mh++)
#pragma unroll
            for (int j = 0; j < 8; j++) {
                int n = n0 + j * 8 + ec;
                float b0 = sBias1[n], b1 = sBias1[n + 1];
                float* cc = c[mh][j];
                int r0 = m0 + mh * 16 + er;
                unsigned short h0, l0, h1, l1;
                split_bf(fmaxf(cc[0] + b0, 0.f), h0, l0);
                split_bf(fmaxf(cc[1] + b1, 0.f), h1, l1);
                *(unsigned*)(smem + SA + r0 * 272 + n * 2) =
                    (unsigned)h0 | ((unsigned)h1 << 16);
                *(unsigned*)(smem + SA + ALO_OFF + r0 * 272 + n * 2) =
                    (unsigned)l0 | ((unsigned)l1 << 16);
                split_bf(fmaxf(cc[2] + b0, 0.f), h0, l0);
                split_bf(fmaxf(cc[3] + b1, 0.f), h1, l1);
                *(unsigned*)(smem + SA + (r0 + 8) * 272 + n * 2) =
                    (unsigned)h0 | ((unsigned)h1 << 16);
                *(unsigned*)(smem + SA + ALO_OFF + (r0 + 8) * 272 + n * 2) =
                    (unsigned)l0 | ((unsigned)l1 << 16);
            }
        __syncthreads();

        mainloop_128(sbase, SWB_HI, lOff, m0, n0, c);
        __syncthreads();

        float* sV = (float*)(smem + SA);
#pragma unroll
        for (int mh = 0; mh < 2; mh++)
#pragma unroll
            for (int j = 0; j < 8; j++) {
                int n = n0 + j * 8 + ec;
                int rr = m0 + mh * 16 + er;
                float b0 = sBias2[n], b1 = sBias2[n + 1];
                float* cc = c[mh][j];
                *(float2*)&sV[rr * 132 + n] =
                    make_float2(fmaxf(cc[0] + b0, 0.f), fmaxf(cc[1] + b1, 0.f));
                *(float2*)&sV[(rr + 8) * 132 + n] =
                    make_float2(fmaxf(cc[2] + b0, 0.f), fmaxf(cc[3] + b1, 0.f));
            }
        if (t < 128) {
            int gr = row0 + t;
            sB[t] = (gr < M) ? load_index(batch, gr, is64) : -1;
        }
        __syncthreads();

        if (t < 128) {
            float s = 0.f, q = 0.f, run = 0.f;
            int cur = sB[0];
            for (int r = 0; r < 128; r++) {
                int b = sB[r];
                if (b != cur) {
                    if (cur >= 0) atomicAdd(&g_gsum[cur * NF + t], run);
                    run = 0.f;
                    cur = b;
                }
                if (b >= 0) {
                    float v = sV[r * 132 + t];
                    run += v;
                    s += v;
                    q += v * v;
                }
            }
            if (cur >= 0) atomicAdd(&g_gsum[cur * NF + t], run);
            atomicAdd(&g_stats[t], s);
            atomicAdd(&g_stats[128 + t], q);
        }
        __syncthreads();

        {
            int nt = tile + gridDim.x;
            if (nt < NTILES) {
                int row0n = nt << 7;
                for (int idx = t; idx < 2048; idx += 256) {
                    int r = idx >> 4, c4 = idx & 15;
                    int gr = row0n + r;
                    int ok = (gr < M) ? 16 : 0;
                    int grc = ok ? gr : 0;
                    cp_async16(sbase + SA + r * 272 + c4 * 16,
                               Ahi + grc * 64 + c4 * 4, ok);
                    cp_async16(sbase + SA + ALO_OFF + r * 272 + c4 * 16,
                               Alo + grc * 64 + c4 * 4, ok);
                }
            }
            CP_COMMIT();
        }
    }
}

// ---------------- fused: BN-affine pool + recurrence + output MLP ----------
#define WT_STRIDE 260
#define RECUR_SMEM ((128 * WT_STRIDE + 128 + 4 * 256 + 96 + 8) * (int)sizeof(float))

__global__ __launch_bounds__(128) void recur_mlp_kernel(
        const void* __restrict__ batch,
        const float* __restrict__ gamma, const float* __restrict__ beta,
        const float* __restrict__ Wl1, const float* __restrict__ bl1,
        const float* __restrict__ Wl2, const float* __restrict__ bl2,
        const float* __restrict__ Wm1, const float* __restrict__ bm1,
        const float* __restrict__ Wm2, const float* __restrict__ bm2,
        float* __restrict__ out) {
    extern __shared__ float sm[];
    float* Wt  = sm;
    float* bs  = Wt + 128 * WT_STRIDE;
    float* cat = bs + 128;
    float* hid = cat + 4 * 256;
    int* se = (int*)(hid + 96);
    int t = threadIdx.x;
    int g0 = blockIdx.x * 4;
    int is64 = probe_is64(batch);

    if (t < 5) {
        int target = g0 + t;
        int lo = 0, hi = N_NODES;
        while (lo < hi) {
            int mid = (lo + hi) >> 1;
            int b = load_index(batch, mid, is64);
            if (b < target) lo = mid + 1; else hi = mid;
        }
        se[t] = lo;
    }

    for (int idx = t; idx < 256 * 64; idx += 128) {
        int k = idx >> 6, c = idx & 63;
        Wt[c * WT_STRIDE + k] = Wl2[idx];
        Wt[(c + 64) * WT_STRIDE + k] = Wl1[idx];
    }
    bs[t] = (t < 64) ? bl2[t] : bl1[t - 64];

    float st0 = g_stats[t];
    float st1 = g_stats[128 + t];
    float gs[4];
#pragma unroll
    for (int r = 0; r < 4; r++) {
        gs[r] = g_gsum[(g0 + r) * NF + t];
        g_gsum[(g0 + r) * NF + t] = 0.f;
    }
    __syncthreads();
    if (t == 0) {
        __threadfence();
        int k = atomicAdd(&g_tickR, 1);
        se[5] = (k == N_GRAPHS / 4 - 1);
    }
    __syncthreads();
    if (se[5]) {
        g_stats[t] = 0.f;
        g_stats[128 + t] = 0.f;
        if (t == 0) g_tickR = 0;
    }

    float mu = st0 / (float)N_NODES;
    float var = st1 / (float)N_NODES - mu * mu;
    float rs = rsqrtf(var + BN_EPS);
    float gm = gamma[t], bt = beta[t];
#pragma unroll
    for (int r = 0; r < 4; r++) {
        int cnt = se[r + 1] - se[r];
        float val = 0.f;
        if (cnt > 0) {
            float m = gs[r] / (float)cnt;
            val = gm * (m - mu) * rs + bt;
        }
        cat[r * 256 + t] = val;
        cat[r * 256 + 128 + t] = val;
    }
    __syncthreads();

    const float* wv0 = &Wt[t * WT_STRIDE];
    float bias = bs[t];
    for (int it = 0; it < N_ITERS; it++) {
        float a0 = bias, a1 = bias, a2 = bias, a3 = bias;
#pragma unroll 8
        for (int k = 0; k < 256; k += 4) {
            float4 wv = *(const float4*)&wv0[k];
            float4 c0 = *(const float4*)&cat[0 * 256 + k];
            float4 c1 = *(const float4*)&cat[1 * 256 + k];
            float4 c2 = *(const float4*)&cat[2 * 256 + k];
            float4 c3 = *(const float4*)&cat[3 * 256 + k];
            a0 += c0.x * wv.x + c0.y * wv.y + c0.z * wv.z + c0.w * wv.w;
            a1 += c1.x * wv.x + c1.y * wv.y + c1.z * wv.z + c1.w * wv.w;
            a2 += c2.x * wv.x + c2.y * wv.y + c2.z * wv.z + c2.w * wv.w;
            a3 += c3.x * wv.x + c3.y * wv.y + c3.z * wv.z + c3.w * wv.w;
        }
        float o[4] = {a0, a1, a2, a3};
        float v[4];
#pragma unroll
        for (int r = 0; r < 4; r++)
            v[r] = (t < 64) ? tanhf(o[r]) : (1.0f / (1.0f + expf(-o[r])));
        __syncthreads();
#pragma unroll
        for (int r = 0; r < 4; r++) cat[r * 256 + 128 + t] = v[r];
        __syncthreads();
    }

    for (int r = 0; r < 4; r++) {
        if (t < DIM) {
            float a = bm1[t];
            const float* h = &cat[r * 256 + 128];
#pragma unroll 8
            for (int k = 0; k < NF; k++) a += h[k] * Wm1[k * DIM + t];
            hid[t] = fmaxf(a, 0.f);
        }
        __syncthreads();
        if (t < N_OUT) {
            float a = bm2[t];
            for (int k = 0; k < DIM; k++) a += hid[k] * Wm2[k * N_OUT + t];
            out[(g0 + r) * N_OUT + t] = a;
        }
        __syncthreads();
    }
}

// ---------------- host ----------------
extern "C" void kernel_launch(void* const* d_in, const int* in_sizes, int n_in,
                              void* d_out, int out_size) {
    const float* x     = (const float*)d_in[0];
    const void*  ei    = d_in[1];
    const void*  batch = d_in[2];
    const float* W1a = (const float*)d_in[3];
    const float* b1a = (const float*)d_in[4];
    const float* W1b = (const float*)d_in[5];
    const float* b1b = (const float*)d_in[6];
    const float* gamma = (const float*)d_in[7];
    const float* beta  = (const float*)d_in[8];
    const float* Wl1 = (const float*)d_in[9];
    const float* bl1 = (const float*)d_in[10];
    const float* Wl2 = (const float*)d_in[11];
    const float* bl2 = (const float*)d_in[12];
    const float* Wm1 = (const float*)d_in[13];
    const float* bm1 = (const float*)d_in[14];
    const float* Wm2 = (const float*)d_in[15];
    const float* bm2 = (const float*)d_in[16];
    float* out = (float*)d_out;

    void *p_ahi, *p_alo;
    cudaGetSymbolAddress(&p_ahi, g_ahi);
    cudaGetSymbolAddress(&p_alo, g_alo);

    cudaFuncSetAttribute(gemm_fused_kernel,
                         cudaFuncAttributeMaxDynamicSharedMemorySize, GEMM_SMEM);
    cudaFuncSetAttribute(recur_mlp_kernel,
                         cudaFuncAttributeMaxDynamicSharedMemorySize, RECUR_SMEM);

    prologue_kernel<<<PRO_GRID, 256>>>((const float4*)x, ei);
    gemm_fused_kernel<<<148, 256, GEMM_SMEM>>>(
        (const unsigned*)p_ahi, (const unsigned*)p_alo,
        W1a, b1a, W1b, b1b, batch, N_NODES);
    recur_mlp_kernel<<<N_GRAPHS / 4, 128, RECUR_SMEM>>>(
        batch, gamma, beta, Wl1, bl1, Wl2, bl2, Wm1, bm1, Wm2, bm2, out);
}

// round 9
// speedup vs baseline: 1.2826x; 1.2826x over previous
#include <cuda_runtime.h>
#include <cuda_bf16.h>
#include <cuda_fp16.h>
#include <math.h>
#include <stdint.h>

#define N_NODES  50000
#define N_EDGES  600000
#define NF       128
#define N_GRAPHS 256
#define DIM      95
#define N_OUT    12
#define N_ITERS  10
#define BN_EPS   1e-5f
#define SCAN_NBLK 196
#define NTILES   391             // ceil(50000/128)

// ---------------- scratch (zero-initialized at load; self-cleaning) --------
__device__ unsigned g_ahi[N_NODES * 64];   // bf16x2 packed: (x+agg) hi
__device__ unsigned g_alo[N_NODES * 64];
__device__ unsigned g_x16[N_NODES * 64];   // x as half2 pairs (2 uints = 4 feats)
__device__ int   g_counts[N_NODES];        // zeroed by scanAB after use
__device__ int   g_offsets[N_NODES + 1];   // block-local prefixes
__device__ int   g_cursor[N_NODES];
__device__ int   g_srcidx[N_EDGES];
__device__ int   g_bsums[SCAN_NBLK];
__device__ int   g_bpre[SCAN_NBLK];
__device__ float g_stats[2 * NF];          // zeroed by recur_mlp last block
__device__ float g_gsum[N_GRAPHS * NF];    // zeroed by its recur_mlp block
__device__ int   g_tickA;                  // self-resetting tickets
__device__ int   g_tickR;

// ---------------- helpers ----------------
__device__ __forceinline__ uint32_t smem_u32(const void* p) {
    uint32_t a;
    asm("{ .reg .u64 t; cvta.to.shared.u64 t, %1; cvt.u32.u64 %0, t; }" : "=r"(a) : "l"(p));
    return a;
}
__device__ __forceinline__ void split_bf(float v, unsigned short& h, unsigned short& l) {
    __nv_bfloat16 hb = __float2bfloat16(v);
    float r = v - __bfloat162float(hb);
    __nv_bfloat16 lb = __float2bfloat16(r);
    h = __bfloat16_as_ushort(hb);
    l = __bfloat16_as_ushort(lb);
}
__device__ __forceinline__ void ldsm_x4(uint32_t* r, uint32_t addr) {
    asm volatile("ldmatrix.sync.aligned.m8n8.x4.shared.b16 {%0,%1,%2,%3}, [%4];"
        : "=r"(r[0]), "=r"(r[1]), "=r"(r[2]), "=r"(r[3]) : "r"(addr));
}
__device__ __forceinline__ void ldsm_x4_t(uint32_t* r, uint32_t addr) {
    asm volatile("ldmatrix.sync.aligned.m8n8.x4.trans.shared.b16 {%0,%1,%2,%3}, [%4];"
        : "=r"(r[0]), "=r"(r[1]), "=r"(r[2]), "=r"(r[3]) : "r"(addr));
}
__device__ __forceinline__ void mma_bf16(float* c, const uint32_t* a,
                                         uint32_t b0, uint32_t b1) {
    asm volatile("mma.sync.aligned.m16n8k16.row.col.f32.bf16.bf16.f32 "
        "{%0,%1,%2,%3}, {%4,%5,%6,%7}, {%8,%9}, {%0,%1,%2,%3};"
        : "+f"(c[0]), "+f"(c[1]), "+f"(c[2]), "+f"(c[3])
        : "r"(a[0]), "r"(a[1]), "r"(a[2]), "r"(a[3]), "r"(b0), "r"(b1));
}
__device__ __forceinline__ void cp_async16(uint32_t dst, const void* src, int srcsz) {
    asm volatile("cp.async.cg.shared.global [%0], [%1], 16, %2;"
        :: "r"(dst), "l"(src), "r"(srcsz) : "memory");
}
#define CP_COMMIT() asm volatile("cp.async.commit_group;" ::: "memory")
#define CP_WAIT0()  asm volatile("cp.async.wait_group 0;" ::: "memory")
__device__ __forceinline__ int load_index(const void* p, long long i, int is64) {
    if (is64) return (int)((const long long*)p)[i];
    return ((const int*)p)[i];
}
__device__ __forceinline__ int probe_is64(const void* p) {
    const int* w32 = (const int*)p;
    int bad = 0;
    for (int j = threadIdx.x; j < 1024; j += blockDim.x)
        if (w32[2 * j + 1] != 0) bad = 1;
    return !__syncthreads_or(bad);
}

// ---------------- CSR: count (+ x -> fp16 conversion, rides under atomics) -
__global__ void count_kernel(const void* ei, const float4* __restrict__ x4) {
    int is64 = probe_is64(ei);
    int gtid = blockIdx.x * blockDim.x + threadIdx.x;
    int gstride = gridDim.x * blockDim.x;
    for (int e = gtid; e < N_EDGES; e += gstride) {
        int d = load_index(ei, (long long)N_EDGES + e, is64);
        atomicAdd(&g_counts[d], 1);
    }
    uint2* x16v2 = (uint2*)g_x16;
    for (int i = gtid; i < N_NODES * 32; i += gstride) {
        float4 v = x4[i];
        __half2 a = __floats2half2_rn(v.x, v.y);
        __half2 b = __floats2half2_rn(v.z, v.w);
        uint2 u;
        u.x = *(unsigned*)&a;
        u.y = *(unsigned*)&b;
        x16v2[i] = u;
    }
}

// ---------------- fused scan (local prefix + last-block scans block sums) --
__global__ void scanAB_kernel() {
    __shared__ int ws[8];
    __shared__ int amLast;
    int t = threadIdx.x, lane = t & 31, w = t >> 5;
    int i = blockIdx.x * 256 + t;
    int v = (i < N_NODES) ? g_counts[i] : 0;
    if (i < N_NODES) g_counts[i] = 0;          // self-clean for next call
    int x = v;
#pragma unroll
    for (int o = 1; o < 32; o <<= 1) {
        int y = __shfl_up_sync(0xffffffffu, x, o);
        if (lane >= o) x += y;
    }
    if (lane == 31) ws[w] = x;
    __syncthreads();
    if (w == 0) {
        int y = (lane < 8) ? ws[lane] : 0;
#pragma unroll
        for (int o = 1; o < 32; o <<= 1) {
            int z = __shfl_up_sync(0xffffffffu, y, o);
            if (lane >= o) y += z;
        }
        if (lane < 8) ws[lane] = y;
    }
    __syncthreads();
    int pre = ((w > 0) ? ws[w - 1] : 0) + x - v;  // block-local exclusive
    if (i <= N_NODES) g_offsets[i] = pre;
    if (i < N_NODES) g_cursor[i] = pre;
    if (t == 255) g_bsums[blockIdx.x] = ws[7];

    if (t == 0) {
        __threadfence();
        int k = atomicAdd(&g_tickA, 1);
        amLast = (k == SCAN_NBLK - 1);
        if (amLast) __threadfence();
    }
    __syncthreads();
    if (amLast) {
        int v2 = (t < SCAN_NBLK) ? g_bsums[t] : 0;
        int x2 = v2;
#pragma unroll
        for (int o = 1; o < 32; o <<= 1) {
            int y = __shfl_up_sync(0xffffffffu, x2, o);
            if (lane >= o) x2 += y;
        }
        __syncthreads();
        if (lane == 31) ws[w] = x2;
        __syncthreads();
        if (w == 0) {
            int y = (lane < 8) ? ws[lane] : 0;
#pragma unroll
            for (int o = 1; o < 32; o <<= 1) {
                int z = __shfl_up_sync(0xffffffffu, y, o);
                if (lane >= o) y += z;
            }
            if (lane < 8) ws[lane] = y;
        }
        __syncthreads();
        if (t < SCAN_NBLK) g_bpre[t] = ((w > 0) ? ws[w - 1] : 0) + x2 - v2;
        if (t == 0) g_tickA = 0;               // self-reset ticket
    }
}

// ---------------- CSR: scatter (bpre added at use) ----------------
__global__ void scatter_kernel(const void* ei) {
    int is64 = probe_is64(ei);
    for (int e = blockIdx.x * blockDim.x + threadIdx.x; e < N_EDGES;
         e += gridDim.x * blockDim.x) {
        int s = load_index(ei, e, is64);
        int d = load_index(ei, (long long)N_EDGES + e, is64);
        int pos = g_bpre[d >> 8] + atomicAdd(&g_cursor[d], 1);
        g_srcidx[pos] = s;
    }
}

// ---------------- GIN aggregation: fp16 gather + fp32 self -> bf16 hi/lo ---
__global__ void agg_kernel(const float4* __restrict__ x4) {
    int node = blockIdx.x * 8 + (threadIdx.x >> 5);
    int lane = threadIdx.x & 31;
    if (node >= N_NODES) return;
    const uint2* x16v2 = (const uint2*)g_x16;
    float4 self = x4[node * 32 + lane];
    float acc0 = self.x, acc1 = self.y, acc2 = self.z, acc3 = self.w;
    int e0 = g_offsets[node] + g_bpre[node >> 8];
    int e1 = g_offsets[node + 1] + g_bpre[(node + 1) >> 8];
    int e = e0;
    int n4 = e0 + ((e1 - e0) & ~3);
    for (; e < n4; e += 4) {
        int s0 = g_srcidx[e], s1 = g_srcidx[e + 1];
        int s2 = g_srcidx[e + 2], s3 = g_srcidx[e + 3];
        uint2 u0 = x16v2[s0 * 32 + lane];
        uint2 u1 = x16v2[s1 * 32 + lane];
        uint2 u2 = x16v2[s2 * 32 + lane];
        uint2 u3 = x16v2[s3 * 32 + lane];
        float2 f0a = __half22float2(*(__half2*)&u0.x);
        float2 f0b = __half22float2(*(__half2*)&u0.y);
        float2 f1a = __half22float2(*(__half2*)&u1.x);
        float2 f1b = __half22float2(*(__half2*)&u1.y);
        float2 f2a = __half22float2(*(__half2*)&u2.x);
        float2 f2b = __half22float2(*(__half2*)&u2.y);
        float2 f3a = __half22float2(*(__half2*)&u3.x);
        float2 f3b = __half22float2(*(__half2*)&u3.y);
        acc0 += f0a.x + f1a.x + f2a.x + f3a.x;
        acc1 += f0a.y + f1a.y + f2a.y + f3a.y;
        acc2 += f0b.x + f1b.x + f2b.x + f3b.x;
        acc3 += f0b.y + f1b.y + f2b.y + f3b.y;
    }
    for (; e < e1; e++) {
        int s = g_srcidx[e];
        uint2 u = x16v2[s * 32 + lane];
        float2 fa = __half22float2(*(__half2*)&u.x);
        float2 fb = __half22float2(*(__half2*)&u.y);
        acc0 += fa.x; acc1 += fa.y; acc2 += fb.x; acc3 += fb.y;
    }
    float vv[4] = {acc0, acc1, acc2, acc3};
    unsigned short h[4], l[4];
#pragma unroll
    for (int i = 0; i < 4; i++) split_bf(vv[i], h[i], l[i]);
    uint2 hv = make_uint2((unsigned)h[0] | ((unsigned)h[1] << 16),
                          (unsigned)h[2] | ((unsigned)h[3] << 16));
    uint2 lv = make_uint2((unsigned)l[0] | ((unsigned)l[1] << 16),
                          (unsigned)l[2] | ((unsigned)l[3] << 16));
    ((uint2*)g_ahi)[node * 32 + lane] = hv;
    ((uint2*)g_alo)[node * 32 + lane] = lv;
}

// ---------------- fused dual GEMM (nn1 both layers) ------------------------
// x1 = relu(relu(A@W1a + b1a)@W1b + b1b), A given as bf16 hi/lo.
// t1 lives only in smem. Epilogue 2: fused BN stats + per-graph pooling.
#define SA      0                 /* A/t1 tile: hi @ +0, lo @ +34816 */
#define ALO_OFF 34816
#define SWA_HI  69632
#define SWA_LO  104448
#define SWB_HI  139264
#define SWB_LO  174080
#define SBIAS1  208896
#define SBIAS2  209408
#define SBATCH  209920
#define GEMM_SMEM 210432

__device__ __forceinline__ void mainloop_128(uint32_t sbase, uint32_t wBase,
                                             uint32_t lOff, int m0, int n0,
                                             float c[2][8][4]) {
#pragma unroll
    for (int mh = 0; mh < 2; mh++)
#pragma unroll
        for (int j = 0; j < 8; j++)
#pragma unroll
            for (int q = 0; q < 4; q++) c[mh][j][q] = 0.f;

#pragma unroll 1
    for (int ks = 0; ks < 8; ks++) {
        uint32_t ah[2][4], al[2][4];
#pragma unroll
        for (int mh = 0; mh < 2; mh++) {
            uint32_t aa = sbase + SA + (uint32_t)(m0 + mh * 16) * 272 +
                          (uint32_t)ks * 32 + lOff;
            ldsm_x4(ah[mh], aa);
            ldsm_x4(al[mh], aa + ALO_OFF);
        }
#pragma unroll
        for (int nj = 0; nj < 4; nj++) {
            uint32_t bh[4], bl[4];
            uint32_t ba = sbase + wBase + (uint32_t)ks * 16 * 272 +
                          (uint32_t)(n0 + nj * 16) * 2 + lOff;
            ldsm_x4_t(bh, ba);
            ldsm_x4_t(bl, ba + ALO_OFF);
#pragma unroll
            for (int mh = 0; mh < 2; mh++) {
                mma_bf16(c[mh][2 * nj],     ah[mh], bh[0], bh[1]);
                mma_bf16(c[mh][2 * nj + 1], ah[mh], bh[2], bh[3]);
                mma_bf16(c[mh][2 * nj],     ah[mh], bl[0], bl[1]);
                mma_bf16(c[mh][2 * nj + 1], ah[mh], bl[2], bl[3]);
                mma_bf16(c[mh][2 * nj],     al[mh], bh[0], bh[1]);
                mma_bf16(c[mh][2 * nj + 1], al[mh], bh[2], bh[3]);
            }
        }
    }
}

__global__ __launch_bounds__(256, 1) void gemm_fused_kernel(
        const unsigned* __restrict__ Ahi, const unsigned* __restrict__ Alo,
        const float* __restrict__ W1a, const float* __restrict__ b1a,
        const float* __restrict__ W1b, const float* __restrict__ b1b,
        const void* __restrict__ batch, int M) {
    extern __shared__ char smem[];
    uint32_t sbase = smem_u32(smem);
    float* sBias1 = (float*)(smem + SBIAS1);
    float* sBias2 = (float*)(smem + SBIAS2);
    int* sB = (int*)(smem + SBATCH);
    int t = threadIdx.x;
    int lane = t & 31;
    int w = t >> 5;
    int wr = w >> 1, wc = w & 1;
    int m0 = wr * 32, n0 = wc * 64;
    int is64 = probe_is64(batch);

    {
        int tile0 = blockIdx.x;
        if (tile0 < NTILES) {
            int row0 = tile0 << 7;
            for (int idx = t; idx < 2048; idx += 256) {
                int r = idx >> 4, c4 = idx & 15;
                int gr = row0 + r;
                int ok = (gr < M) ? 16 : 0;
                int grc = ok ? gr : 0;
                cp_async16(sbase + SA + r * 272 + c4 * 16, Ahi + grc * 64 + c4 * 4, ok);
                cp_async16(sbase + SA + ALO_OFF + r * 272 + c4 * 16,
                           Alo + grc * 64 + c4 * 4, ok);
            }
        }
        CP_COMMIT();
    }

    for (int idx = t; idx < 128 * 128; idx += 256) {
        int k = idx >> 7, n = idx & 127;
        unsigned short h, l;
        split_bf(W1a[idx], h, l);
        *(unsigned short*)(smem + SWA_HI + (k * 136 + n) * 2) = h;
        *(unsigned short*)(smem + SWA_LO + (k * 136 + n) * 2) = l;
        split_bf(W1b[idx], h, l);
        *(unsigned short*)(smem + SWB_HI + (k * 136 + n) * 2) = h;
        *(unsigned short*)(smem + SWB_LO + (k * 136 + n) * 2) = l;
    }
    if (t < 128) { sBias1[t] = b1a[t]; sBias2[t] = b1b[t]; }

    int lrow = (lane & 7) + ((lane >> 3) & 1) * 8;
    int lcol = (lane >> 4) * 8;
    uint32_t lOff = (uint32_t)(lrow * 136 + lcol) * 2;
    int er = lane >> 2;
    int ec = 2 * (lane & 3);

    for (int tile = blockIdx.x; tile < NTILES; tile += gridDim.x) {
        int row0 = tile << 7;
        CP_WAIT0();
        __syncthreads();

        float c[2][8][4];
        mainloop_128(sbase, SWA_HI, lOff, m0, n0, c);
        __syncthreads();

#pragma unroll
        for (int mh = 0; mh < 2; mh++)
#pragma unroll
            for (int j = 0; j < 8; j++) {
                int n = n0 + j * 8 + ec;
                float b0 = sBias1[n], b1 = sBias1[n + 1];
                float* cc = c[mh][j];
                int r0 = m0 + mh * 16 + er;
                unsigned short h0, l0, h1, l1;
                split_bf(fmaxf(cc[0] + b0, 0.f), h0, l0);
                split_bf(fmaxf(cc[1] + b1, 0.f), h1, l1);
                *(unsigned*)(smem + SA + r0 * 272 + n * 2) =
                    (unsigned)h0 | ((unsigned)h1 << 16);
                *(unsigned*)(smem + SA + ALO_OFF + r0 * 272 + n * 2) =
                    (unsigned)l0 | ((unsigned)l1 << 16);
                split_bf(fmaxf(cc[2] + b0, 0.f), h0, l0);
                split_bf(fmaxf(cc[3] + b1, 0.f), h1, l1);
                *(unsigned*)(smem + SA + (r0 + 8) * 272 + n * 2) =
                    (unsigned)h0 | ((unsigned)h1 << 16);
                *(unsigned*)(smem + SA + ALO_OFF + (r0 + 8) * 272 + n * 2) =
                    (unsigned)l0 | ((unsigned)l1 << 16);
            }
        __syncthreads();

        mainloop_128(sbase, SWB_HI, lOff, m0, n0, c);
        __syncthreads();

        float* sV = (float*)(smem + SA);
#pragma unroll
        for (int mh = 0; mh < 2; mh++)
#pragma unroll
            for (int j = 0; j < 8; j++) {
                int n = n0 + j * 8 + ec;
                int rr = m0 + mh * 16 + er;
                float b0 = sBias2[n], b1 = sBias2[n + 1];
                float* cc = c[mh][j];
                *(float2*)&sV[rr * 132 + n] =
                    make_float2(fmaxf(cc[0] + b0, 0.f), fmaxf(cc[1] + b1, 0.f));
                *(float2*)&sV[(rr + 8) * 132 + n] =
                    make_float2(fmaxf(cc[2] + b0, 0.f), fmaxf(cc[3] + b1, 0.f));
            }
        if (t < 128) {
            int gr = row0 + t;
            sB[t] = (gr < M) ? load_index(batch, gr, is64) : -1;
        }
        __syncthreads();

        if (t < 128) {
            float s = 0.f, q = 0.f, run = 0.f;
            int cur = sB[0];
            for (int r = 0; r < 128; r++) {
                int b = sB[r];
                if (b != cur) {
                    if (cur >= 0) atomicAdd(&g_gsum[cur * NF + t], run);
                    run = 0.f;
                    cur = b;
                }
                if (b >= 0) {
                    float v = sV[r * 132 + t];
                    run += v;
                    s += v;
                    q += v * v;
                }
            }
            if (cur >= 0) atomicAdd(&g_gsum[cur * NF + t], run);
            atomicAdd(&g_stats[t], s);
            atomicAdd(&g_stats[128 + t], q);
        }
        __syncthreads();

        {
            int nt = tile + gridDim.x;
            if (nt < NTILES) {
                int row0n = nt << 7;
                for (int idx = t; idx < 2048; idx += 256) {
                    int r = idx >> 4, c4 = idx & 15;
                    int gr = row0n + r;
                    int ok = (gr < M) ? 16 : 0;
                    int grc = ok ? gr : 0;
                    cp_async16(sbase + SA + r * 272 + c4 * 16,
                               Ahi + grc * 64 + c4 * 4, ok);
                    cp_async16(sbase + SA + ALO_OFF + r * 272 + c4 * 16,
                               Alo + grc * 64 + c4 * 4, ok);
                }
            }
            CP_COMMIT();
        }
    }
}

// ---------------- fused: BN-affine pool + recurrence + output MLP ----------
#define WT_STRIDE 260
#define RECUR_SMEM ((128 * WT_STRIDE + 128 + 4 * 256 + 96 + 8) * (int)sizeof(float))

__global__ __launch_bounds__(128) void recur_mlp_kernel(
        const void* __restrict__ batch,
        const float* __restrict__ gamma, const float* __restrict__ beta,
        const float* __restrict__ Wl1, const float* __restrict__ bl1,
        const float* __restrict__ Wl2, const float* __restrict__ bl2,
        const float* __restrict__ Wm1, const float* __restrict__ bm1,
        const float* __restrict__ Wm2, const float* __restrict__ bm2,
        float* __restrict__ out) {
    extern __shared__ float sm[];
    float* Wt  = sm;
    float* bs  = Wt + 128 * WT_STRIDE;
    float* cat = bs + 128;
    float* hid = cat + 4 * 256;
    int* se = (int*)(hid + 96);
    int t = threadIdx.x;
    int g0 = blockIdx.x * 4;
    int is64 = probe_is64(batch);

    if (t < 5) {
        int target = g0 + t;
        int lo = 0, hi = N_NODES;
        while (lo < hi) {
            int mid = (lo + hi) >> 1;
            int b = load_index(batch, mid, is64);
            if (b < target) lo = mid + 1; else hi = mid;
        }
        se[t] = lo;
    }

    for (int idx = t; idx < 256 * 64; idx += 128) {
        int k = idx >> 6, c = idx & 63;
        Wt[c * WT_STRIDE + k] = Wl2[idx];
        Wt[(c + 64) * WT_STRIDE + k] = Wl1[idx];
    }
    bs[t] = (t < 64) ? bl2[t] : bl1[t - 64];

    float st0 = g_stats[t];
    float st1 = g_stats[128 + t];
    float gs[4];
#pragma unroll
    for (int r = 0; r < 4; r++) {
        gs[r] = g_gsum[(g0 + r) * NF + t];
        g_gsum[(g0 + r) * NF + t] = 0.f;
    }
    __syncthreads();
    if (t == 0) {
        __threadfence();
        int k = atomicAdd(&g_tickR, 1);
        se[5] = (k == N_GRAPHS / 4 - 1);
    }
    __syncthreads();
    if (se[5]) {
        g_stats[t] = 0.f;
        g_stats[128 + t] = 0.f;
        if (t == 0) g_tickR = 0;
    }

    float mu = st0 / (float)N_NODES;
    float var = st1 / (float)N_NODES - mu * mu;
    float rs = rsqrtf(var + BN_EPS);
    float gm = gamma[t], bt = beta[t];
#pragma unroll
    for (int r = 0; r < 4; r++) {
        int cnt = se[r + 1] - se[r];
        float val = 0.f;
        if (cnt > 0) {
            float m = gs[r] / (float)cnt;
            val = gm * (m - mu) * rs + bt;
        }
        cat[r * 256 + t] = val;
        cat[r * 256 + 128 + t] = val;
    }
    __syncthreads();

    const float* wv0 = &Wt[t * WT_STRIDE];
    float bias = bs[t];
    for (int it = 0; it < N_ITERS; it++) {
        float a0 = bias, a1 = bias, a2 = bias, a3 = bias;
#pragma unroll 8
        for (int k = 0; k < 256; k += 4) {
            float4 wv = *(const float4*)&wv0[k];
            float4 c0 = *(const float4*)&cat[0 * 256 + k];
            float4 c1 = *(const float4*)&cat[1 * 256 + k];
            float4 c2 = *(const float4*)&cat[2 * 256 + k];
            float4 c3 = *(const float4*)&cat[3 * 256 + k];
            a0 += c0.x * wv.x + c0.y * wv.y + c0.z * wv.z + c0.w * wv.w;
            a1 += c1.x * wv.x + c1.y * wv.y + c1.z * wv.z + c1.w * wv.w;
            a2 += c2.x * wv.x + c2.y * wv.y + c2.z * wv.z + c2.w * wv.w;
            a3 += c3.x * wv.x + c3.y * wv.y + c3.z * wv.z + c3.w * wv.w;
        }
        float o[4] = {a0, a1, a2, a3};
        float v[4];
#pragma unroll
        for (int r = 0; r < 4; r++)
            v[r] = (t < 64) ? tanhf(o[r]) : (1.0f / (1.0f + expf(-o[r])));
        __syncthreads();
#pragma unroll
        for (int r = 0; r < 4; r++) cat[r * 256 + 128 + t] = v[r];
        __syncthreads();
    }

    for (int r = 0; r < 4; r++) {
        if (t < DIM) {
            float a = bm1[t];
            const float* h = &cat[r * 256 + 128];
#pragma unroll 8
            for (int k = 0; k < NF; k++) a += h[k] * Wm1[k * DIM + t];
            hid[t] = fmaxf(a, 0.f);
        }
        __syncthreads();
        if (t < N_OUT) {
            float a = bm2[t];
            for (int k = 0; k < DIM; k++) a += hid[k] * Wm2[k * N_OUT + t];
            out[(g0 + r) * N_OUT + t] = a;
        }
        __syncthreads();
    }
}

// ---------------- host ----------------
extern "C" void kernel_launch(void* const* d_in, const int* in_sizes, int n_in,
                              void* d_out, int out_size) {
    const float* x     = (const float*)d_in[0];
    const void*  ei    = d_in[1];
    const void*  batch = d_in[2];
    const float* W1a = (const float*)d_in[3];
    const float* b1a = (const float*)d_in[4];
    const float* W1b = (const float*)d_in[5];
    const float* b1b = (const float*)d_in[6];
    const float* gamma = (const float*)d_in[7];
    const float* beta  = (const float*)d_in[8];
    const float* Wl1 = (const float*)d_in[9];
    const float* bl1 = (const float*)d_in[10];
    const float* Wl2 = (const float*)d_in[11];
    const float* bl2 = (const float*)d_in[12];
    const float* Wm1 = (const float*)d_in[13];
    const float* bm1 = (const float*)d_in[14];
    const float* Wm2 = (const float*)d_in[15];
    const float* bm2 = (const float*)d_in[16];
    float* out = (float*)d_out;

    void *p_ahi, *p_alo;
    cudaGetSymbolAddress(&p_ahi, g_ahi);
    cudaGetSymbolAddress(&p_alo, g_alo);

    cudaFuncSetAttribute(gemm_fused_kernel,
                         cudaFuncAttributeMaxDynamicSharedMemorySize, GEMM_SMEM);
    cudaFuncSetAttribute(recur_mlp_kernel,
                         cudaFuncAttributeMaxDynamicSharedMemorySize, RECUR_SMEM);

    count_kernel<<<512, 256>>>(ei, (const float4*)x);
    scanAB_kernel<<<SCAN_NBLK, 256>>>();
    scatter_kernel<<<512, 256>>>(ei);
    agg_kernel<<<(N_NODES + 7) / 8, 256>>>((const float4*)x);
    gemm_fused_kernel<<<148, 256, GEMM_SMEM>>>(
        (const unsigned*)p_ahi, (const unsigned*)p_alo,
        W1a, b1a, W1b, b1b, batch, N_NODES);
    recur_mlp_kernel<<<N_GRAPHS / 4, 128, RECUR_SMEM>>>(
        batch, gamma, beta, Wl1, bl1, Wl2, bl2, Wm1, bm1, Wm2, bm2, out);
}

// round 10
// speedup vs baseline: 1.3906x; 1.0842x over previous
#include <cuda_runtime.h>
#include <cuda_bf16.h>
#include <math.h>
#include <stdint.h>

#define N_NODES  50000
#define N_EDGES  600000
#define NF       128
#define N_GRAPHS 256
#define DIM      95
#define N_OUT    12
#define N_ITERS  10
#define BN_EPS   1e-5f
#define SCAN_NBLK 196
#define NTILES   391             // ceil(50000/128)
#define CSR_GRID 512             // all-resident: __launch_bounds__(256,4) -> 592 cap

// ---------------- scratch (zero-initialized at load; self-cleaning) --------
__device__ unsigned g_ahi[N_NODES * 64];   // bf16x2 packed: (x+agg) hi
__device__ unsigned g_alo[N_NODES * 64];
__device__ int   g_counts[N_NODES];        // zeroed in scan phase
__device__ int   g_offsets[N_NODES + 1];   // chunk-local prefixes
__device__ int   g_cursor[N_NODES];
__device__ int   g_srcidx[N_EDGES];
__device__ int   g_bsums[SCAN_NBLK];
__device__ int   g_bpre[SCAN_NBLK];
__device__ float g_stats[2 * NF];          // zeroed by recur_mlp last block
__device__ float g_gsum[N_GRAPHS * NF];    // zeroed by its recur_mlp block
__device__ int   g_arrive;                 // csr grid barrier (self-reset)
__device__ int   g_tickR;                  // recur ticket (self-reset)

// ---------------- helpers ----------------
__device__ __forceinline__ uint32_t smem_u32(const void* p) {
    uint32_t a;
    asm("{ .reg .u64 t; cvta.to.shared.u64 t, %1; cvt.u32.u64 %0, t; }" : "=r"(a) : "l"(p));
    return a;
}
__device__ __forceinline__ void split_bf(float v, unsigned short& h, unsigned short& l) {
    __nv_bfloat16 hb = __float2bfloat16(v);
    float r = v - __bfloat162float(hb);
    __nv_bfloat16 lb = __float2bfloat16(r);
    h = __bfloat16_as_ushort(hb);
    l = __bfloat16_as_ushort(lb);
}
__device__ __forceinline__ void ldsm_x4(uint32_t* r, uint32_t addr) {
    asm volatile("ldmatrix.sync.aligned.m8n8.x4.shared.b16 {%0,%1,%2,%3}, [%4];"
        : "=r"(r[0]), "=r"(r[1]), "=r"(r[2]), "=r"(r[3]) : "r"(addr));
}
__device__ __forceinline__ void ldsm_x4_t(uint32_t* r, uint32_t addr) {
    asm volatile("ldmatrix.sync.aligned.m8n8.x4.trans.shared.b16 {%0,%1,%2,%3}, [%4];"
        : "=r"(r[0]), "=r"(r[1]), "=r"(r[2]), "=r"(r[3]) : "r"(addr));
}
__device__ __forceinline__ void mma_bf16(float* c, const uint32_t* a,
                                         uint32_t b0, uint32_t b1) {
    asm volatile("mma.sync.aligned.m16n8k16.row.col.f32.bf16.bf16.f32 "
        "{%0,%1,%2,%3}, {%4,%5,%6,%7}, {%8,%9}, {%0,%1,%2,%3};"
        : "+f"(c[0]), "+f"(c[1]), "+f"(c[2]), "+f"(c[3])
        : "r"(a[0]), "r"(a[1]), "r"(a[2]), "r"(a[3]), "r"(b0), "r"(b1));
}
__device__ __forceinline__ void cp_async16(uint32_t dst, const void* src, int srcsz) {
    asm volatile("cp.async.cg.shared.global [%0], [%1], 16, %2;"
        :: "r"(dst), "l"(src), "r"(srcsz) : "memory");
}
#define CP_COMMIT() asm volatile("cp.async.commit_group;" ::: "memory")
#define CP_WAIT0()  asm volatile("cp.async.wait_group 0;" ::: "memory")
__device__ __forceinline__ int load_index(const void* p, long long i, int is64) {
    if (is64) return (int)((const long long*)p)[i];
    return ((const int*)p)[i];
}
__device__ __forceinline__ int probe_is64(const void* p) {
    const int* w32 = (const int*)p;
    int bad = 0;
    for (int j = threadIdx.x; j < 1024; j += blockDim.x)
        if (w32[2 * j + 1] != 0) bad = 1;
    return !__syncthreads_or(bad);
}
// grid barrier: monotonic arrive counter within one launch (all blocks resident)
__device__ __forceinline__ void grid_bar(int phase) {
    __syncthreads();
    if (threadIdx.x == 0) {
        __threadfence();
        atomicAdd(&g_arrive, 1);
        int target = phase * (int)gridDim.x;
        while (atomicAdd(&g_arrive, 0) < target) __nanosleep(64);
        __threadfence();
    }
    __syncthreads();
}

// ---------------- merged CSR build: count -> scan -> scatter ---------------
__global__ __launch_bounds__(256, 4) void csr_kernel(const void* ei) {
    __shared__ int ws[8];
    int t = threadIdx.x, lane = t & 31, w = t >> 5;
    int gtid = blockIdx.x * 256 + t;
    int gstride = gridDim.x * 256;
    int is64 = probe_is64(ei);

    // phase 1: degree count
    for (int e = gtid; e < N_EDGES; e += gstride) {
        int d = load_index(ei, (long long)N_EDGES + e, is64);
        atomicAdd(&g_counts[d], 1);
    }
    grid_bar(1);

    // phase 2: per-chunk local exclusive scans (+ self-clean counts)
    for (int chunk = blockIdx.x; chunk < SCAN_NBLK; chunk += gridDim.x) {
        int i = chunk * 256 + t;
        int v = (i < N_NODES) ? g_counts[i] : 0;
        if (i < N_NODES) g_counts[i] = 0;
        int x = v;
#pragma unroll
        for (int o = 1; o < 32; o <<= 1) {
            int y = __shfl_up_sync(0xffffffffu, x, o);
            if (lane >= o) x += y;
        }
        if (lane == 31) ws[w] = x;
        __syncthreads();
        if (w == 0) {
            int y = (lane < 8) ? ws[lane] : 0;
#pragma unroll
            for (int o = 1; o < 32; o <<= 1) {
                int z = __shfl_up_sync(0xffffffffu, y, o);
                if (lane >= o) y += z;
            }
            if (lane < 8) ws[lane] = y;
        }
        __syncthreads();
        int pre = ((w > 0) ? ws[w - 1] : 0) + x - v;
        if (i <= N_NODES) g_offsets[i] = pre;
        if (i < N_NODES) g_cursor[i] = pre;
        if (t == 255) g_bsums[chunk] = ws[7];
        __syncthreads();
    }
    grid_bar(2);

    // phase 3: block 0 scans the chunk sums -> g_bpre
    if (blockIdx.x == 0) {
        int v2 = (t < SCAN_NBLK) ? g_bsums[t] : 0;
        int x2 = v2;
#pragma unroll
        for (int o = 1; o < 32; o <<= 1) {
            int y = __shfl_up_sync(0xffffffffu, x2, o);
            if (lane >= o) x2 += y;
        }
        if (lane == 31) ws[w] = x2;
        __syncthreads();
        if (w == 0) {
            int y = (lane < 8) ? ws[lane] : 0;
#pragma unroll
            for (int o = 1; o < 32; o <<= 1) {
                int z = __shfl_up_sync(0xffffffffu, y, o);
                if (lane >= o) y += z;
            }
            if (lane < 8) ws[lane] = y;
        }
        __syncthreads();
        if (t < SCAN_NBLK) g_bpre[t] = ((w > 0) ? ws[w - 1] : 0) + x2 - v2;
    }
    grid_bar(3);

    // phase 4: scatter edges into CSR
    for (int e = gtid; e < N_EDGES; e += gstride) {
        int s = load_index(ei, e, is64);
        int d = load_index(ei, (long long)N_EDGES + e, is64);
        int pos = g_bpre[d >> 8] + atomicAdd(&g_cursor[d], 1);
        g_srcidx[pos] = s;
    }

    // final ticket: last block resets the barrier counter (determinism)
    __syncthreads();
    if (t == 0) {
        __threadfence();
        if (atomicAdd(&g_arrive, 1) == 4 * (int)gridDim.x - 1) g_arrive = 0;
    }
}

// ---------------- GIN aggregation (fp32 gather) -> bf16 hi/lo --------------
__global__ void agg_kernel(const float4* __restrict__ x4) {
    int node = blockIdx.x * 8 + (threadIdx.x >> 5);
    int lane = threadIdx.x & 31;
    if (node >= N_NODES) return;
    float4 acc = x4[node * 32 + lane];
    int e0 = g_offsets[node] + g_bpre[node >> 8];
    int e1 = g_offsets[node + 1] + g_bpre[(node + 1) >> 8];
    int e = e0;
    int n4 = e0 + ((e1 - e0) & ~3);
    for (; e < n4; e += 4) {
        int s0 = g_srcidx[e], s1 = g_srcidx[e + 1];
        int s2 = g_srcidx[e + 2], s3 = g_srcidx[e + 3];
        float4 v0 = x4[s0 * 32 + lane];
        float4 v1 = x4[s1 * 32 + lane];
        float4 v2 = x4[s2 * 32 + lane];
        float4 v3 = x4[s3 * 32 + lane];
        acc.x += v0.x + v1.x + v2.x + v3.x;
        acc.y += v0.y + v1.y + v2.y + v3.y;
        acc.z += v0.z + v1.z + v2.z + v3.z;
        acc.w += v0.w + v1.w + v2.w + v3.w;
    }
    for (; e < e1; e++) {
        int s = g_srcidx[e];
        float4 v = x4[s * 32 + lane];
        acc.x += v.x; acc.y += v.y; acc.z += v.z; acc.w += v.w;
    }
    float vv[4] = {acc.x, acc.y, acc.z, acc.w};
    unsigned short h[4], l[4];
#pragma unroll
    for (int i = 0; i < 4; i++) split_bf(vv[i], h[i], l[i]);
    uint2 hv = make_uint2((unsigned)h[0] | ((unsigned)h[1] << 16),
                          (unsigned)h[2] | ((unsigned)h[3] << 16));
    uint2 lv = make_uint2((unsigned)l[0] | ((unsigned)l[1] << 16),
                          (unsigned)l[2] | ((unsigned)l[3] << 16));
    ((uint2*)g_ahi)[node * 32 + lane] = hv;
    ((uint2*)g_alo)[node * 32 + lane] = lv;
}

// ---------------- fused dual GEMM (nn1 both layers) ------------------------
// x1 = relu(relu(A@W1a + b1a)@W1b + b1b), A given as bf16 hi/lo.
// t1 lives only in smem. Epilogue 2: fused BN stats + per-graph pooling.
#define SA      0                 /* A/t1 tile: hi @ +0, lo @ +34816 */
#define ALO_OFF 34816
#define SWA_HI  69632
#define SWA_LO  104448
#define SWB_HI  139264
#define SWB_LO  174080
#define SBIAS1  208896
#define SBIAS2  209408
#define SBATCH  209920
#define GEMM_SMEM 210432

__device__ __forceinline__ void mainloop_128(uint32_t sbase, uint32_t wBase,
                                             uint32_t lOff, int m0, int n0,
                                             float c[2][8][4]) {
#pragma unroll
    for (int mh = 0; mh < 2; mh++)
#pragma unroll
        for (int j = 0; j < 8; j++)
#pragma unroll
            for (int q = 0; q < 4; q++) c[mh][j][q] = 0.f;

#pragma unroll 1
    for (int ks = 0; ks < 8; ks++) {
        uint32_t ah[2][4], al[2][4];
#pragma unroll
        for (int mh = 0; mh < 2; mh++) {
            uint32_t aa = sbase + SA + (uint32_t)(m0 + mh * 16) * 272 +
                          (uint32_t)ks * 32 + lOff;
            ldsm_x4(ah[mh], aa);
            ldsm_x4(al[mh], aa + ALO_OFF);
        }
#pragma unroll
        for (int nj = 0; nj < 4; nj++) {
            uint32_t bh[4], bl[4];
            uint32_t ba = sbase + wBase + (uint32_t)ks * 16 * 272 +
                          (uint32_t)(n0 + nj * 16) * 2 + lOff;
            ldsm_x4_t(bh, ba);
            ldsm_x4_t(bl, ba + ALO_OFF);
#pragma unroll
            for (int mh = 0; mh < 2; mh++) {
                mma_bf16(c[mh][2 * nj],     ah[mh], bh[0], bh[1]);
                mma_bf16(c[mh][2 * nj + 1], ah[mh], bh[2], bh[3]);
                mma_bf16(c[mh][2 * nj],     ah[mh], bl[0], bl[1]);
                mma_bf16(c[mh][2 * nj + 1], ah[mh], bl[2], bl[3]);
                mma_bf16(c[mh][2 * nj],     al[mh], bh[0], bh[1]);
                mma_bf16(c[mh][2 * nj + 1], al[mh], bh[2], bh[3]);
            }
        }
    }
}

__global__ __launch_bounds__(256, 1) void gemm_fused_kernel(
        const unsigned* __restrict__ Ahi, const unsigned* __restrict__ Alo,
        const float* __restrict__ W1a, const float* __restrict__ b1a,
        const float* __restrict__ W1b, const float* __restrict__ b1b,
        const void* __restrict__ batch, int M) {
    extern __shared__ char smem[];
    uint32_t sbase = smem_u32(smem);
    float* sBias1 = (float*)(smem + SBIAS1);
    float* sBias2 = (float*)(smem + SBIAS2);
    int* sB = (int*)(smem + SBATCH);
    int t = threadIdx.x;
    int lane = t & 31;
    int w = t >> 5;
    int wr = w >> 1, wc = w & 1;
    int m0 = wr * 32, n0 = wc * 64;
    int is64 = probe_is64(batch);

    {
        int tile0 = blockIdx.x;
        if (tile0 < NTILES) {
            int row0 = tile0 << 7;
            for (int idx = t; idx < 2048; idx += 256) {
                int r = idx >> 4, c4 = idx & 15;
                int gr = row0 + r;
                int ok = (gr < M) ? 16 : 0;
                int grc = ok ? gr : 0;
                cp_async16(sbase + SA + r * 272 + c4 * 16, Ahi + grc * 64 + c4 * 4, ok);
                cp_async16(sbase + SA + ALO_OFF + r * 272 + c4 * 16,
                           Alo + grc * 64 + c4 * 4, ok);
            }
        }
        CP_COMMIT();
    }

    for (int idx = t; idx < 128 * 128; idx += 256) {
        int k = idx >> 7, n = idx & 127;
        unsigned short h, l;
        split_bf(W1a[idx], h, l);
        *(unsigned short*)(smem + SWA_HI + (k * 136 + n) * 2) = h;
        *(unsigned short*)(smem + SWA_LO + (k * 136 + n) * 2) = l;
        split_bf(W1b[idx], h, l);
        *(unsigned short*)(smem + SWB_HI + (k * 136 + n) * 2) = h;
        *(unsigned short*)(smem + SWB_LO + (k * 136 + n) * 2) = l;
    }
    if (t < 128) { sBias1[t] = b1a[t]; sBias2[t] = b1b[t]; }

    int lrow = (lane & 7) + ((lane >> 3) & 1) * 8;
    int lcol = (lane >> 4) * 8;
    uint32_t lOff = (uint32_t)(lrow * 136 + lcol) * 2;
    int er = lane >> 2;
    int ec = 2 * (lane & 3);

    for (int tile = blockIdx.x; tile < NTILES; tile += gridDim.x) {
        int row0 = tile << 7;
        CP_WAIT0();
        __syncthreads();

        float c[2][8][4];
        mainloop_128(sbase, SWA_HI, lOff, m0, n0, c);
        __syncthreads();

#pragma unroll
        for (int mh = 0; mh < 2; mh++)
#pragma unroll
            for (int j = 0; j < 8; j++) {
                int n = n0 + j * 8 + ec;
                float b0 = sBias1[n], b1 = sBias1[n + 1];
                float* cc = c[mh][j];
                int r0 = m0 + mh * 16 + er;
                unsigned short h0, l0, h1, l1;
                split_bf(fmaxf(cc[0] + b0, 0.f), h0, l0);
                split_bf(fmaxf(cc[1] + b1, 0.f), h1, l1);
                *(unsigned*)(smem + SA + r0 * 272 + n * 2) =
                    (unsigned)h0 | ((unsigned)h1 << 16);
                *(unsigned*)(smem + SA + ALO_OFF + r0 * 272 + n * 2) =
                    (unsigned)l0 | ((unsigned)l1 << 16);
                split_bf(fmaxf(cc[2] + b0, 0.f), h0, l0);
                split_bf(fmaxf(cc[3] + b1, 0.f), h1, l1);
                *(unsigned*)(smem + SA + (r0 + 8) * 272 + n * 2) =
                    (unsigned)h0 | ((unsigned)h1 << 16);
                *(unsigned*)(smem + SA + ALO_OFF + (r0 + 8) * 272 + n * 2) =
                    (unsigned)l0 | ((unsigned)l1 << 16);
            }
        __syncthreads();

        mainloop_128(sbase, SWB_HI, lOff, m0, n0, c);
        __syncthreads();

        float* sV = (float*)(smem + SA);
#pragma unroll
        for (int mh = 0; mh < 2; mh++)
#pragma unroll
            for (int j = 0; j < 8; j++) {
                int n = n0 + j * 8 + ec;
                int rr = m0 + mh * 16 + er;
                float b0 = sBias2[n], b1 = sBias2[n + 1];
                float* cc = c[mh][j];
                *(float2*)&sV[rr * 132 + n] =
                    make_float2(fmaxf(cc[0] + b0, 0.f), fmaxf(cc[1] + b1, 0.f));
                *(float2*)&sV[(rr + 8) * 132 + n] =
                    make_float2(fmaxf(cc[2] + b0, 0.f), fmaxf(cc[3] + b1, 0.f));
            }
        if (t < 128) {
            int gr = row0 + t;
            sB[t] = (gr < M) ? load_index(batch, gr, is64) : -1;
        }
        __syncthreads();

        if (t < 128) {
            float s = 0.f, q = 0.f, run = 0.f;
            int cur = sB[0];
            for (int r = 0; r < 128; r++) {
                int b = sB[r];
                if (b != cur) {
                    if (cur >= 0) atomicAdd(&g_gsum[cur * NF + t], run);
                    run = 0.f;
                    cur = b;
                }
                if (b >= 0) {
                    float v = sV[r * 132 + t];
                    run += v;
                    s += v;
                    q += v * v;
                }
            }
            if (cur >= 0) atomicAdd(&g_gsum[cur * NF + t], run);
            atomicAdd(&g_stats[t], s);
            atomicAdd(&g_stats[128 + t], q);
        }
        __syncthreads();

        {
            int nt = tile + gridDim.x;
            if (nt < NTILES) {
                int row0n = nt << 7;
                for (int idx = t; idx < 2048; idx += 256) {
                    int r = idx >> 4, c4 = idx & 15;
                    int gr = row0n + r;
                    int ok = (gr < M) ? 16 : 0;
                    int grc = ok ? gr : 0;
                    cp_async16(sbase + SA + r * 272 + c4 * 16,
                               Ahi + grc * 64 + c4 * 4, ok);
                    cp_async16(sbase + SA + ALO_OFF + r * 272 + c4 * 16,
                               Alo + grc * 64 + c4 * 4, ok);
                }
            }
            CP_COMMIT();
        }
    }
}

// ---------------- fused: BN-affine pool + recurrence + output MLP ----------
#define WT_STRIDE 260
#define RECUR_SMEM ((128 * WT_STRIDE + 128 + 4 * 256 + 96 + 8) * (int)sizeof(float))

__global__ __launch_bounds__(128) void recur_mlp_kernel(
        const void* __restrict__ batch,
        const float* __restrict__ gamma, const float* __restrict__ beta,
        const float* __restrict__ Wl1, const float* __restrict__ bl1,
        const float* __restrict__ Wl2, const float* __restrict__ bl2,
        const float* __restrict__ Wm1, const float* __restrict__ bm1,
        const float* __restrict__ Wm2, const float* __restrict__ bm2,
        float* __restrict__ out) {
    extern __shared__ float sm[];
    float* Wt  = sm;
    float* bs  = Wt + 128 * WT_STRIDE;
    float* cat = bs + 128;
    float* hid = cat + 4 * 256;
    int* se = (int*)(hid + 96);
    int t = threadIdx.x;
    int g0 = blockIdx.x * 4;
    int is64 = probe_is64(batch);

    if (t < 5) {
        int target = g0 + t;
        int lo = 0, hi = N_NODES;
        while (lo < hi) {
            int mid = (lo + hi) >> 1;
            int b = load_index(batch, mid, is64);
            if (b < target) lo = mid + 1; else hi = mid;
        }
        se[t] = lo;
    }

    for (int idx = t; idx < 256 * 64; idx += 128) {
        int k = idx >> 6, c = idx & 63;
        Wt[c * WT_STRIDE + k] = Wl2[idx];
        Wt[(c + 64) * WT_STRIDE + k] = Wl1[idx];
    }
    bs[t] = (t < 64) ? bl2[t] : bl1[t - 64];

    float st0 = g_stats[t];
    float st1 = g_stats[128 + t];
    float gs[4];
#pragma unroll
    for (int r = 0; r < 4; r++) {
        gs[r] = g_gsum[(g0 + r) * NF + t];
        g_gsum[(g0 + r) * NF + t] = 0.f;
    }
    __syncthreads();
    if (t == 0) {
        __threadfence();
        int k = atomicAdd(&g_tickR, 1);
        se[5] = (k == N_GRAPHS / 4 - 1);
    }
    __syncthreads();
    if (se[5]) {
        g_stats[t] = 0.f;
        g_stats[128 + t] = 0.f;
        if (t == 0) g_tickR = 0;
    }

    float mu = st0 / (float)N_NODES;
    float var = st1 / (float)N_NODES - mu * mu;
    float rs = rsqrtf(var + BN_EPS);
    float gm = gamma[t], bt = beta[t];
#pragma unroll
    for (int r = 0; r < 4; r++) {
        int cnt = se[r + 1] - se[r];
        float val = 0.f;
        if (cnt > 0) {
            float m = gs[r] / (float)cnt;
            val = gm * (m - mu) * rs + bt;
        }
        cat[r * 256 + t] = val;
        cat[r * 256 + 128 + t] = val;
    }
    __syncthreads();

    const float* wv0 = &Wt[t * WT_STRIDE];
    float bias = bs[t];
    for (int it = 0; it < N_ITERS; it++) {
        float a0 = bias, a1 = bias, a2 = bias, a3 = bias;
#pragma unroll 8
        for (int k = 0; k < 256; k += 4) {
            float4 wv = *(const float4*)&wv0[k];
            float4 c0 = *(const float4*)&cat[0 * 256 + k];
            float4 c1 = *(const float4*)&cat[1 * 256 + k];
            float4 c2 = *(const float4*)&cat[2 * 256 + k];
            float4 c3 = *(const float4*)&cat[3 * 256 + k];
            a0 += c0.x * wv.x + c0.y * wv.y + c0.z * wv.z + c0.w * wv.w;
            a1 += c1.x * wv.x + c1.y * wv.y + c1.z * wv.z + c1.w * wv.w;
            a2 += c2.x * wv.x + c2.y * wv.y + c2.z * wv.z + c2.w * wv.w;
            a3 += c3.x * wv.x + c3.y * wv.y + c3.z * wv.z + c3.w * wv.w;
        }
        float o[4] = {a0, a1, a2, a3};
        float v[4];
#pragma unroll
        for (int r = 0; r < 4; r++)
            v[r] = (t < 64) ? tanhf(o[r]) : (1.0f / (1.0f + expf(-o[r])));
        __syncthreads();
#pragma unroll
        for (int r = 0; r < 4; r++) cat[r * 256 + 128 + t] = v[r];
        __syncthreads();
    }

    for (int r = 0; r < 4; r++) {
        if (t < DIM) {
            float a = bm1[t];
            const float* h = &cat[r * 256 + 128];
#pragma unroll 8
            for (int k = 0; k < NF; k++) a += h[k] * Wm1[k * DIM + t];
            hid[t] = fmaxf(a, 0.f);
        }
        __syncthreads();
        if (t < N_OUT) {
            float a = bm2[t];
            for (int k = 0; k < DIM; k++) a += hid[k] * Wm2[k * N_OUT + t];
            out[(g0 + r) * N_OUT + t] = a;
        }
        __syncthreads();
    }
}

// ---------------- host ----------------
extern "C" void kernel_launch(void* const* d_in, const int* in_sizes, int n_in,
                              void* d_out, int out_size) {
    const float* x     = (const float*)d_in[0];
    const void*  ei    = d_in[1];
    const void*  batch = d_in[2];
    const float* W1a = (const float*)d_in[3];
    const float* b1a = (const float*)d_in[4];
    const float* W1b = (const float*)d_in[5];
    const float* b1b = (const float*)d_in[6];
    const float* gamma = (const float*)d_in[7];
    const float* beta  = (const float*)d_in[8];
    const float* Wl1 = (const float*)d_in[9];
    const float* bl1 = (const float*)d_in[10];
    const float* Wl2 = (const float*)d_in[11];
    const float* bl2 = (const float*)d_in[12];
    const float* Wm1 = (const float*)d_in[13];
    const float* bm1 = (const float*)d_in[14];
    const float* Wm2 = (const float*)d_in[15];
    const float* bm2 = (const float*)d_in[16];
    float* out = (float*)d_out;

    void *p_ahi, *p_alo;
    cudaGetSymbolAddress(&p_ahi, g_ahi);
    cudaGetSymbolAddress(&p_alo, g_alo);

    cudaFuncSetAttribute(gemm_fused_kernel,
                         cudaFuncAttributeMaxDynamicSharedMemorySize, GEMM_SMEM);
    cudaFuncSetAttribute(recur_mlp_kernel,
                         cudaFuncAttributeMaxDynamicSharedMemorySize, RECUR_SMEM);

    csr_kernel<<<CSR_GRID, 256>>>(ei);
    agg_kernel<<<(N_NODES + 7) / 8, 256>>>((const float4*)x);
    gemm_fused_kernel<<<148, 256, GEMM_SMEM>>>(
        (const unsigned*)p_ahi, (const unsigned*)p_alo,
        W1a, b1a, W1b, b1b, batch, N_NODES);
    recur_mlp_kernel<<<N_GRAPHS / 4, 128, RECUR_SMEM>>>(
        batch, gamma, beta, Wl1, bl1, Wl2, bl2, Wm1, bm1, Wm2, bm2, out);
}

// round 11
// speedup vs baseline: 1.6814x; 1.2091x over previous
#include <cuda_runtime.h>
#include <cuda_bf16.h>
#include <math.h>
#include <stdint.h>

#define N_NODES  50000
#define N_EDGES  600000
#define NF       128
#define N_GRAPHS 256
#define DIM      95
#define N_OUT    12
#define N_ITERS  10
#define BN_EPS   1e-5f
#define SCAN_NBLK 196
#define NTILES   391             // ceil(50000/128)

// ---------------- scratch (zero-initialized at load; self-cleaning) --------
__device__ unsigned g_ahi[N_NODES * 64];   // bf16x2 packed: (x+agg) hi
__device__ unsigned g_alo[N_NODES * 64];
__device__ int   g_counts[N_NODES];        // zeroed by scanAB after use
__device__ int   g_offsets[N_NODES + 1];   // block-local prefixes
__device__ int   g_cursor[N_NODES];
__device__ int   g_srcidx[N_EDGES];
__device__ int   g_bsums[SCAN_NBLK];
__device__ int   g_bpre[SCAN_NBLK];
__device__ float g_stats[2 * NF];          // zeroed by recur_mlp last block
__device__ float g_gsum[N_GRAPHS * NF];    // zeroed by its recur_mlp block
__device__ int   g_tickA;                  // self-resetting tickets
__device__ int   g_tickR;

// ---------------- helpers ----------------
__device__ __forceinline__ uint32_t smem_u32(const void* p) {
    uint32_t a;
    asm("{ .reg .u64 t; cvta.to.shared.u64 t, %1; cvt.u32.u64 %0, t; }" : "=r"(a) : "l"(p));
    return a;
}
__device__ __forceinline__ void split_bf(float v, unsigned short& h, unsigned short& l) {
    __nv_bfloat16 hb = __float2bfloat16(v);
    float r = v - __bfloat162float(hb);
    __nv_bfloat16 lb = __float2bfloat16(r);
    h = __bfloat16_as_ushort(hb);
    l = __bfloat16_as_ushort(lb);
}
__device__ __forceinline__ void ldsm_x4(uint32_t* r, uint32_t addr) {
    asm volatile("ldmatrix.sync.aligned.m8n8.x4.shared.b16 {%0,%1,%2,%3}, [%4];"
        : "=r"(r[0]), "=r"(r[1]), "=r"(r[2]), "=r"(r[3]) : "r"(addr));
}
__device__ __forceinline__ void ldsm_x4_t(uint32_t* r, uint32_t addr) {
    asm volatile("ldmatrix.sync.aligned.m8n8.x4.trans.shared.b16 {%0,%1,%2,%3}, [%4];"
        : "=r"(r[0]), "=r"(r[1]), "=r"(r[2]), "=r"(r[3]) : "r"(addr));
}
__device__ __forceinline__ void mma_bf16(float* c, const uint32_t* a,
                                         uint32_t b0, uint32_t b1) {
    asm volatile("mma.sync.aligned.m16n8k16.row.col.f32.bf16.bf16.f32 "
        "{%0,%1,%2,%3}, {%4,%5,%6,%7}, {%8,%9}, {%0,%1,%2,%3};"
        : "+f"(c[0]), "+f"(c[1]), "+f"(c[2]), "+f"(c[3])
        : "r"(a[0]), "r"(a[1]), "r"(a[2]), "r"(a[3]), "r"(b0), "r"(b1));
}
__device__ __forceinline__ void cp_async16(uint32_t dst, const void* src, int srcsz) {
    asm volatile("cp.async.cg.shared.global [%0], [%1], 16, %2;"
        :: "r"(dst), "l"(src), "r"(srcsz) : "memory");
}
#define CP_COMMIT() asm volatile("cp.async.commit_group;" ::: "memory")
#define CP_WAIT0()  asm volatile("cp.async.wait_group 0;" ::: "memory")
__device__ __forceinline__ int load_index(const void* p, long long i, int is64) {
    if (is64) return (int)((const long long*)p)[i];
    return ((const int*)p)[i];
}
__device__ __forceinline__ int probe_is64(const void* p) {
    const int* w32 = (const int*)p;
    int bad = 0;
    for (int j = threadIdx.x; j < 1024; j += blockDim.x)
        if (w32[2 * j + 1] != 0) bad = 1;
    return !__syncthreads_or(bad);
}

// ---------------- CSR: count ----------------
__global__ void count_kernel(const void* ei) {
    int is64 = probe_is64(ei);
    for (int e = blockIdx.x * blockDim.x + threadIdx.x; e < N_EDGES;
         e += gridDim.x * blockDim.x) {
        int d = load_index(ei, (long long)N_EDGES + e, is64);
        atomicAdd(&g_counts[d], 1);
    }
}

// ---------------- fused scan (local prefix + last-block scans block sums) --
__global__ void scanAB_kernel() {
    __shared__ int ws[8];
    __shared__ int amLast;
    int t = threadIdx.x, lane = t & 31, w = t >> 5;
    int i = blockIdx.x * 256 + t;
    int v = (i < N_NODES) ? g_counts[i] : 0;
    if (i < N_NODES) g_counts[i] = 0;          // self-clean for next call
    int x = v;
#pragma unroll
    for (int o = 1; o < 32; o <<= 1) {
        int y = __shfl_up_sync(0xffffffffu, x, o);
        if (lane >= o) x += y;
    }
    if (lane == 31) ws[w] = x;
    __syncthreads();
    if (w == 0) {
        int y = (lane < 8) ? ws[lane] : 0;
#pragma unroll
        for (int o = 1; o < 32; o <<= 1) {
            int z = __shfl_up_sync(0xffffffffu, y, o);
            if (lane >= o) y += z;
        }
        if (lane < 8) ws[lane] = y;
    }
    __syncthreads();
    int pre = ((w > 0) ? ws[w - 1] : 0) + x - v;  // block-local exclusive
    if (i <= N_NODES) g_offsets[i] = pre;
    if (i < N_NODES) g_cursor[i] = pre;
    if (t == 255) g_bsums[blockIdx.x] = ws[7];

    if (t == 0) {
        __threadfence();
        int k = atomicAdd(&g_tickA, 1);
        amLast = (k == SCAN_NBLK - 1);
        if (amLast) __threadfence();
    }
    __syncthreads();
    if (amLast) {
        int v2 = (t < SCAN_NBLK) ? g_bsums[t] : 0;
        int x2 = v2;
#pragma unroll
        for (int o = 1; o < 32; o <<= 1) {
            int y = __shfl_up_sync(0xffffffffu, x2, o);
            if (lane >= o) x2 += y;
        }
        __syncthreads();
        if (lane == 31) ws[w] = x2;
        __syncthreads();
        if (w == 0) {
            int y = (lane < 8) ? ws[lane] : 0;
#pragma unroll
            for (int o = 1; o < 32; o <<= 1) {
                int z = __shfl_up_sync(0xffffffffu, y, o);
                if (lane >= o) y += z;
            }
            if (lane < 8) ws[lane] = y;
        }
        __syncthreads();
        if (t < SCAN_NBLK) g_bpre[t] = ((w > 0) ? ws[w - 1] : 0) + x2 - v2;
        if (t == 0) g_tickA = 0;               // self-reset ticket
    }
}

// ---------------- CSR: scatter (bpre added at use) ----------------
__global__ void scatter_kernel(const void* ei) {
    int is64 = probe_is64(ei);
    for (int e = blockIdx.x * blockDim.x + threadIdx.x; e < N_EDGES;
         e += gridDim.x * blockDim.x) {
        int s = load_index(ei, e, is64);
        int d = load_index(ei, (long long)N_EDGES + e, is64);
        int pos = g_bpre[d >> 8] + atomicAdd(&g_cursor[d], 1);
        g_srcidx[pos] = s;
    }
}

// ---------------- GIN aggregation (fp32 gather) -> bf16 hi/lo --------------
__global__ void agg_kernel(const float4* __restrict__ x4) {
    int node = blockIdx.x * 8 + (threadIdx.x >> 5);
    int lane = threadIdx.x & 31;
    if (node >= N_NODES) return;
    float4 acc = x4[node * 32 + lane];
    int e0 = g_offsets[node] + g_bpre[node >> 8];
    int e1 = g_offsets[node + 1] + g_bpre[(node + 1) >> 8];
    int e = e0;
    int n4 = e0 + ((e1 - e0) & ~3);
    for (; e < n4; e += 4) {
        int s0 = g_srcidx[e], s1 = g_srcidx[e + 1];
        int s2 = g_srcidx[e + 2], s3 = g_srcidx[e + 3];
        float4 v0 = x4[s0 * 32 + lane];
        float4 v1 = x4[s1 * 32 + lane];
        float4 v2 = x4[s2 * 32 + lane];
        float4 v3 = x4[s3 * 32 + lane];
        acc.x += v0.x + v1.x + v2.x + v3.x;
        acc.y += v0.y + v1.y + v2.y + v3.y;
        acc.z += v0.z + v1.z + v2.z + v3.z;
        acc.w += v0.w + v1.w + v2.w + v3.w;
    }
    for (; e < e1; e++) {
        int s = g_srcidx[e];
        float4 v = x4[s * 32 + lane];
        acc.x += v.x; acc.y += v.y; acc.z += v.z; acc.w += v.w;
    }
    float vv[4] = {acc.x, acc.y, acc.z, acc.w};
    unsigned short h[4], l[4];
#pragma unroll
    for (int i = 0; i < 4; i++) split_bf(vv[i], h[i], l[i]);
    uint2 hv = make_uint2((unsigned)h[0] | ((unsigned)h[1] << 16),
                          (unsigned)h[2] | ((unsigned)h[3] << 16));
    uint2 lv = make_uint2((unsigned)l[0] | ((unsigned)l[1] << 16),
                          (unsigned)l[2] | ((unsigned)l[3] << 16));
    ((uint2*)g_ahi)[node * 32 + lane] = hv;
    ((uint2*)g_alo)[node * 32 + lane] = lv;
}

// ---------------- fused dual GEMM (nn1 both layers) ------------------------
// x1 = relu(relu(A@W1a + b1a)@W1b + b1b), A given as bf16 hi/lo.
// t1 lives only in smem. Epilogue 2: fused BN stats + per-graph pooling.
#define SA      0                 /* A/t1 tile: hi @ +0, lo @ +34816 */
#define ALO_OFF 34816
#define SWA_HI  69632
#define SWA_LO  104448
#define SWB_HI  139264
#define SWB_LO  174080
#define SBIAS1  208896
#define SBIAS2  209408
#define SBATCH  209920
#define GEMM_SMEM 210432

__device__ __forceinline__ void mainloop_128(uint32_t sbase, uint32_t wBase,
                                             uint32_t lOff, int m0, int n0,
                                             float c[2][8][4]) {
#pragma unroll
    for (int mh = 0; mh < 2; mh++)
#pragma unroll
        for (int j = 0; j < 8; j++)
#pragma unroll
            for (int q = 0; q < 4; q++) c[mh][j][q] = 0.f;

#pragma unroll 1
    for (int ks = 0; ks < 8; ks++) {
        uint32_t ah[2][4], al[2][4];
#pragma unroll
        for (int mh = 0; mh < 2; mh++) {
            uint32_t aa = sbase + SA + (uint32_t)(m0 + mh * 16) * 272 +
                          (uint32_t)ks * 32 + lOff;
            ldsm_x4(ah[mh], aa);
            ldsm_x4(al[mh], aa + ALO_OFF);
        }
#pragma unroll
        for (int nj = 0; nj < 4; nj++) {
            uint32_t bh[4], bl[4];
            uint32_t ba = sbase + wBase + (uint32_t)ks * 16 * 272 +
                          (uint32_t)(n0 + nj * 16) * 2 + lOff;
            ldsm_x4_t(bh, ba);
            ldsm_x4_t(bl, ba + ALO_OFF);
#pragma unroll
            for (int mh = 0; mh < 2; mh++) {
                mma_bf16(c[mh][2 * nj],     ah[mh], bh[0], bh[1]);
                mma_bf16(c[mh][2 * nj + 1], ah[mh], bh[2], bh[3]);
                mma_bf16(c[mh][2 * nj],     ah[mh], bl[0], bl[1]);
                mma_bf16(c[mh][2 * nj + 1], ah[mh], bl[2], bl[3]);
                mma_bf16(c[mh][2 * nj],     al[mh], bh[0], bh[1]);
                mma_bf16(c[mh][2 * nj + 1], al[mh], bh[2], bh[3]);
            }
        }
    }
}

__global__ __launch_bounds__(256, 1) void gemm_fused_kernel(
        const unsigned* __restrict__ Ahi, const unsigned* __restrict__ Alo,
        const float* __restrict__ W1a, const float* __restrict__ b1a,
        const float* __restrict__ W1b, const float* __restrict__ b1b,
        const void* __restrict__ batch, int M) {
    extern __shared__ char smem[];
    uint32_t sbase = smem_u32(smem);
    float* sBias1 = (float*)(smem + SBIAS1);
    float* sBias2 = (float*)(smem + SBIAS2);
    int* sB = (int*)(smem + SBATCH);
    int t = threadIdx.x;
    int lane = t & 31;
    int w = t >> 5;
    int wr = w >> 1, wc = w & 1;
    int m0 = wr * 32, n0 = wc * 64;
    int is64 = probe_is64(batch);

    {
        int tile0 = blockIdx.x;
        if (tile0 < NTILES) {
            int row0 = tile0 << 7;
            for (int idx = t; idx < 2048; idx += 256) {
                int r = idx >> 4, c4 = idx & 15;
                int gr = row0 + r;
                int ok = (gr < M) ? 16 : 0;
                int grc = ok ? gr : 0;
                cp_async16(sbase + SA + r * 272 + c4 * 16, Ahi + grc * 64 + c4 * 4, ok);
                cp_async16(sbase + SA + ALO_OFF + r * 272 + c4 * 16,
                           Alo + grc * 64 + c4 * 4, ok);
            }
        }
        CP_COMMIT();
    }

    for (int idx = t; idx < 128 * 128; idx += 256) {
        int k = idx >> 7, n = idx & 127;
        unsigned short h, l;
        split_bf(W1a[idx], h, l);
        *(unsigned short*)(smem + SWA_HI + (k * 136 + n) * 2) = h;
        *(unsigned short*)(smem + SWA_LO + (k * 136 + n) * 2) = l;
        split_bf(W1b[idx], h, l);
        *(unsigned short*)(smem + SWB_HI + (k * 136 + n) * 2) = h;
        *(unsigned short*)(smem + SWB_LO + (k * 136 + n) * 2) = l;
    }
    if (t < 128) { sBias1[t] = b1a[t]; sBias2[t] = b1b[t]; }

    int lrow = (lane & 7) + ((lane >> 3) & 1) * 8;
    int lcol = (lane >> 4) * 8;
    uint32_t lOff = (uint32_t)(lrow * 136 + lcol) * 2;
    int er = lane >> 2;
    int ec = 2 * (lane & 3);

    for (int tile = blockIdx.x; tile < NTILES; tile += gridDim.x) {
        int row0 = tile << 7;
        CP_WAIT0();
        __syncthreads();

        float c[2][8][4];
        mainloop_128(sbase, SWA_HI, lOff, m0, n0, c);
        __syncthreads();

#pragma unroll
        for (int mh = 0; mh < 2; mh++)
#pragma unroll
            for (int j = 0; j < 8; j++) {
                int n = n0 + j * 8 + ec;
                float b0 = sBias1[n], b1 = sBias1[n + 1];
                float* cc = c[mh][j];
                int r0 = m0 + mh * 16 + er;
                unsigned short h0, l0, h1, l1;
                split_bf(fmaxf(cc[0] + b0, 0.f), h0, l0);
                split_bf(fmaxf(cc[1] + b1, 0.f), h1, l1);
                *(unsigned*)(smem + SA + r0 * 272 + n * 2) =
                    (unsigned)h0 | ((unsigned)h1 << 16);
                *(unsigned*)(smem + SA + ALO_OFF + r0 * 272 + n * 2) =
                    (unsigned)l0 | ((unsigned)l1 << 16);
                split_bf(fmaxf(cc[2] + b0, 0.f), h0, l0);
                split_bf(fmaxf(cc[3] + b1, 0.f), h1, l1);
                *(unsigned*)(smem + SA + (r0 + 8) * 272 + n * 2) =
                    (unsigned)h0 | ((unsigned)h1 << 16);
                *(unsigned*)(smem + SA + ALO_OFF + (r0 + 8) * 272 + n * 2) =
                    (unsigned)l0 | ((unsigned)l1 << 16);
            }
        __syncthreads();

        mainloop_128(sbase, SWB_HI, lOff, m0, n0, c);
        __syncthreads();

        float* sV = (float*)(smem + SA);
#pragma unroll
        for (int mh = 0; mh < 2; mh++)
#pragma unroll
            for (int j = 0; j < 8; j++) {
                int n = n0 + j * 8 + ec;
                int rr = m0 + mh * 16 + er;
                float b0 = sBias2[n], b1 = sBias2[n + 1];
                float* cc = c[mh][j];
                *(float2*)&sV[rr * 132 + n] =
                    make_float2(fmaxf(cc[0] + b0, 0.f), fmaxf(cc[1] + b1, 0.f));
                *(float2*)&sV[(rr + 8) * 132 + n] =
                    make_float2(fmaxf(cc[2] + b0, 0.f), fmaxf(cc[3] + b1, 0.f));
            }
        if (t < 128) {
            int gr = row0 + t;
            sB[t] = (gr < M) ? load_index(batch, gr, is64) : -1;
        }
        __syncthreads();

        if (t < 128) {
            float s = 0.f, q = 0.f, run = 0.f;
            int cur = sB[0];
            for (int r = 0; r < 128; r++) {
                int b = sB[r];
                if (b != cur) {
                    if (cur >= 0) atomicAdd(&g_gsum[cur * NF + t], run);
                    run = 0.f;
                    cur = b;
                }
                if (b >= 0) {
                    float v = sV[r * 132 + t];
                    run += v;
                    s += v;
                    q += v * v;
                }
            }
            if (cur >= 0) atomicAdd(&g_gsum[cur * NF + t], run);
            atomicAdd(&g_stats[t], s);
            atomicAdd(&g_stats[128 + t], q);
        }
        __syncthreads();

        {
            int nt = tile + gridDim.x;
            if (nt < NTILES) {
                int row0n = nt << 7;
                for (int idx = t; idx < 2048; idx += 256) {
                    int r = idx >> 4, c4 = idx & 15;
                    int gr = row0n + r;
                    int ok = (gr < M) ? 16 : 0;
                    int grc = ok ? gr : 0;
                    cp_async16(sbase + SA + r * 272 + c4 * 16,
                               Ahi + grc * 64 + c4 * 4, ok);
                    cp_async16(sbase + SA + ALO_OFF + r * 272 + c4 * 16,
                               Alo + grc * 64 + c4 * 4, ok);
                }
            }
            CP_COMMIT();
        }
    }
}

// ---------------- fused: BN-affine pool + recurrence + output MLP ----------
// One graph per block, 512 threads: thread = (col c in [0,128), quarter q).
// Recurrence weights live in REGISTERS (64/thread); cat reads are broadcast
// LDS (conflict-free). Fixes the 4-way-bank-conflict + 6% occupancy disaster
// of the smem-transposed-weight version.
__global__ __launch_bounds__(512, 1) void recur_mlp_kernel(
        const void* __restrict__ batch,
        const float* __restrict__ gamma, const float* __restrict__ beta,
        const float* __restrict__ Wl1, const float* __restrict__ bl1,
        const float* __restrict__ Wl2, const float* __restrict__ bl2,
        const float* __restrict__ Wm1, const float* __restrict__ bm1,
        const float* __restrict__ Wm2, const float* __restrict__ bm2,
        float* __restrict__ out) {
    __shared__ float cat[256];     // [xg(128) | h(128)] for this graph
    __shared__ float part[512];
    __shared__ float hid[DIM];
    __shared__ int se[3];          // [start, end, lastflag]
    int t = threadIdx.x;
    int g = blockIdx.x;
    int c = t & 127;
    int q = t >> 7;                // 0..3 (k-quarter)
    int is64 = probe_is64(batch);

    if (t < 2) {
        int target = g + t;
        int lo = 0, hi = N_NODES;
        while (lo < hi) {
            int mid = (lo + hi) >> 1;
            int b = load_index(batch, mid, is64);
            if (b < target) lo = mid + 1; else hi = mid;
        }
        se[t] = lo;
    }

    // recurrence weights -> registers (coalesced over c; L2-hot across blocks)
    float wreg[64];
    {
        const float* Wsrc = (c < 64) ? (Wl2 + c) : (Wl1 + (c - 64));
        int kbase = q * 64;
#pragma unroll
        for (int i = 0; i < 64; i++) wreg[i] = Wsrc[(kbase + i) * 64];
    }
    float bias = 0.f;
    if (t < 128) bias = (t < 64) ? bl2[t] : bl1[t - 64];

    // stats + own gsum (read, then ticketed zeroing)
    float ss = 0.f, sq = 0.f, gsv = 0.f;
    if (t < 128) {
        ss = g_stats[t];
        sq = g_stats[128 + t];
        gsv = g_gsum[g * NF + t];
        g_gsum[g * NF + t] = 0.f;
    }
    __syncthreads();
    if (t == 0) {
        __threadfence();
        int k = atomicAdd(&g_tickR, 1);
        se[2] = (k == N_GRAPHS - 1);
    }
    __syncthreads();
    if (se[2]) {
        if (t < 256) g_stats[t] = 0.f;
        if (t == 0) g_tickR = 0;
    }

    if (t < 128) {
        int cnt = se[1] - se[0];
        float mu = ss / (float)N_NODES;
        float var = sq / (float)N_NODES - mu * mu;
        float val = 0.f;
        if (cnt > 0) {
            float m = gsv / (float)cnt;
            val = gamma[t] * (m - mu) * rsqrtf(var + BN_EPS) + beta[t];
        }
        cat[t] = val;            // xg half (constant)
        cat[128 + t] = val;      // h init = xg
    }
    __syncthreads();

    for (int it = 0; it < N_ITERS; it++) {
        const float* ck = &cat[q * 64];
        float a0 = 0.f, a1 = 0.f, a2 = 0.f, a3 = 0.f;
#pragma unroll
        for (int i = 0; i < 64; i += 4) {
            float4 cv = *(const float4*)&ck[i];
            a0 += wreg[i] * cv.x;
            a1 += wreg[i + 1] * cv.y;
            a2 += wreg[i + 2] * cv.z;
            a3 += wreg[i + 3] * cv.w;
        }
        part[t] = (a0 + a1) + (a2 + a3);
        __syncthreads();
        if (t < 128) {
            float o = part[t] + part[t + 128] + part[t + 256] + part[t + 384] + bias;
            float v = (t < 64) ? tanhf(o) : (1.0f / (1.0f + expf(-o)));
            cat[128 + t] = v;
        }
        __syncthreads();
    }

    // output MLP for this graph
    if (t < DIM) {
        float a = bm1[t];
        const float* h = &cat[128];
#pragma unroll 8
        for (int k = 0; k < NF; k++) a += h[k] * Wm1[k * DIM + t];
        hid[t] = fmaxf(a, 0.f);
    }
    __syncthreads();
    if (t < N_OUT) {
        float a = bm2[t];
        for (int k = 0; k < DIM; k++) a += hid[k] * Wm2[k * N_OUT + t];
        out[g * N_OUT + t] = a;
    }
}

// ---------------- host ----------------
extern "C" void kernel_launch(void* const* d_in, const int* in_sizes, int n_in,
                              void* d_out, int out_size) {
    const float* x     = (const float*)d_in[0];
    const void*  ei    = d_in[1];
    const void*  batch = d_in[2];
    const float* W1a = (const float*)d_in[3];
    const float* b1a = (const float*)d_in[4];
    const float* W1b = (const float*)d_in[5];
    const float* b1b = (const float*)d_in[6];
    const float* gamma = (const float*)d_in[7];
    const float* beta  = (const float*)d_in[8];
    const float* Wl1 = (const float*)d_in[9];
    const float* bl1 = (const float*)d_in[10];
    const float* Wl2 = (const float*)d_in[11];
    const float* bl2 = (const float*)d_in[12];
    const float* Wm1 = (const float*)d_in[13];
    const float* bm1 = (const float*)d_in[14];
    const float* Wm2 = (const float*)d_in[15];
    const float* bm2 = (const float*)d_in[16];
    float* out = (float*)d_out;

    void *p_ahi, *p_alo;
    cudaGetSymbolAddress(&p_ahi, g_ahi);
    cudaGetSymbolAddress(&p_alo, g_alo);

    cudaFuncSetAttribute(gemm_fused_kernel,
                         cudaFuncAttributeMaxDynamicSharedMemorySize, GEMM_SMEM);

    count_kernel<<<512, 256>>>(ei);
    scanAB_kernel<<<SCAN_NBLK, 256>>>();
    scatter_kernel<<<512, 256>>>(ei);
    agg_kernel<<<(N_NODES + 7) / 8, 256>>>((const float4*)x);
    gemm_fused_kernel<<<148, 256, GEMM_SMEM>>>(
        (const unsigned*)p_ahi, (const unsigned*)p_alo,
        W1a, b1a, W1b, b1b, batch, N_NODES);
    recur_mlp_kernel<<<N_GRAPHS, 512>>>(
        batch, gamma, beta, Wl1, bl1, Wl2, bl2, Wm1, bm1, Wm2, bm2, out);
}